// round 4
// baseline (speedup 1.0000x reference)
#include <cuda_runtime.h>
#include <cuda_bf16.h>

// GGIN: 3-layer GIN + graph readout. N=100000, E=1600000, D=128, G=1024, L=3, C=128.
// R4: gather fused into GEMM prologue (no m buffer), k4-chunked mainloop,
//     parallel scan, fused init kernels.

#define D 128
#define MAXN 100000
#define MAXG 1024
#define MAXE 1600000

__device__ float g_h0[(size_t)MAXN * D];
__device__ float g_h1[(size_t)MAXN * D];
__device__ float g_hgA[MAXG * D];
__device__ float g_hgB[MAXG * D];
__device__ float g_ctx[MAXG * D];
__device__ float g_pg[MAXG * D];
__device__ float g_t[MAXG * D];
__device__ float g_lead[D];
__device__ int   g_rowptr[MAXN + 1];
__device__ int   g_cursor[MAXN];
__device__ int   g_csr[MAXE];
__device__ int   g_bsum[256];

__device__ __forceinline__ void red4(float* p, float4 v) {
    asm volatile("red.global.add.v4.f32 [%0], {%1,%2,%3,%4};"
                 :: "l"(p), "f"(v.x), "f"(v.y), "f"(v.z), "f"(v.w) : "memory");
}
__device__ __forceinline__ unsigned long long pack2(float x, float y) {
    unsigned long long r;
    asm("mov.b64 %0, {%1,%2};" : "=l"(r) : "f"(x), "f"(y));
    return r;
}
__device__ __forceinline__ void fma2(unsigned long long& d, unsigned long long a, unsigned long long b) {
    asm("fma.rn.f32x2 %0, %1, %2, %0;" : "+l"(d) : "l"(a), "l"(b));
}
__device__ __forceinline__ float2 unpack2(unsigned long long v) {
    float2 r;
    asm("mov.b64 {%0,%1}, %2;" : "=f"(r.x), "=f"(r.y) : "l"(v));
    return r;
}

// ---- zero ----
__global__ void k_zero(float4* __restrict__ p, int n4) {
    int stride = gridDim.x * blockDim.x;
    for (int i = blockIdx.x * blockDim.x + threadIdx.x; i < n4; i += stride)
        p[i] = make_float4(0.f, 0.f, 0.f, 0.f);
}
__global__ void k_zeroi(int* __restrict__ p, int n) {
    int i = blockIdx.x * blockDim.x + threadIdx.x;
    if (i < n) p[i] = 0;
}

// ================= CSR build =================
__global__ void k_hist(const int* __restrict__ dst, int* __restrict__ deg, int nE) {
    int e = blockIdx.x * blockDim.x + threadIdx.x;
    if (e < nE) atomicAdd(deg + __ldg(dst + e), 1);
}
__global__ void k_bsum(const int* __restrict__ deg, int* __restrict__ bsum, int n) {
    __shared__ int sh[8];
    int base = blockIdx.x * 1024 + threadIdx.x * 4;
    int s = 0;
    #pragma unroll
    for (int j = 0; j < 4; j++) { int i = base + j; if (i < n) s += deg[i]; }
    #pragma unroll
    for (int o = 16; o > 0; o >>= 1) s += __shfl_down_sync(0xffffffffu, s, o);
    if ((threadIdx.x & 31) == 0) sh[threadIdx.x >> 5] = s;
    __syncthreads();
    if (threadIdx.x == 0) {
        int t = 0;
        for (int w = 0; w < 8; w++) t += sh[w];
        bsum[blockIdx.x] = t;
    }
}
// single-block parallel exclusive scan of chunk sums (nb <= 256); sets rowptr[n]=E
__global__ void k_scanblk(int* __restrict__ bsum, int nb, int* __restrict__ rowptr, int n, int nE) {
    __shared__ int ws[8];
    __shared__ int wexc[8];
    int tid = threadIdx.x;
    int lane = tid & 31, warp = tid >> 5;
    int v = (tid < nb) ? bsum[tid] : 0;
    int p = v;
    #pragma unroll
    for (int o = 1; o < 32; o <<= 1) {
        int t = __shfl_up_sync(0xffffffffu, p, o);
        if (lane >= o) p += t;
    }
    if (lane == 31) ws[warp] = p;
    __syncthreads();
    if (tid == 0) {
        int acc = 0;
        #pragma unroll
        for (int w = 0; w < 8; w++) { wexc[w] = acc; acc += ws[w]; }
        rowptr[n] = nE;
    }
    __syncthreads();
    if (tid < nb) bsum[tid] = p - v + wexc[warp];
}
__global__ void k_scanfin(int* __restrict__ deg, const int* __restrict__ bsum,
                          int* __restrict__ rowptr, int* __restrict__ cursor, int n) {
    __shared__ int wsum[8];
    __shared__ int wexc[8];
    int lane = threadIdx.x & 31, warp = threadIdx.x >> 5;
    int base = blockIdx.x * 1024 + threadIdx.x * 4;
    int v[4]; int s = 0;
    #pragma unroll
    for (int j = 0; j < 4; j++) { int i = base + j; v[j] = (i < n) ? deg[i] : 0; s += v[j]; }
    int pre = s;
    #pragma unroll
    for (int o = 1; o < 32; o <<= 1) {
        int t = __shfl_up_sync(0xffffffffu, pre, o);
        if (lane >= o) pre += t;
    }
    int excl = pre - s;
    if (lane == 31) wsum[warp] = pre;
    __syncthreads();
    if (threadIdx.x == 0) {
        int acc = 0;
        #pragma unroll
        for (int w = 0; w < 8; w++) { wexc[w] = acc; acc += wsum[w]; }
    }
    __syncthreads();
    int off = bsum[blockIdx.x] + wexc[warp] + excl;
    #pragma unroll
    for (int j = 0; j < 4; j++) {
        int i = base + j;
        if (i < n) { rowptr[i] = off; cursor[i] = off; off += v[j]; }
    }
}
__global__ void k_fill(const int* __restrict__ src, const int* __restrict__ dst,
                       int* __restrict__ cursor, int* __restrict__ csr, int nE) {
    int e = blockIdx.x * blockDim.x + threadIdx.x;
    if (e < nE) {
        int pos = atomicAdd(cursor + __ldg(dst + e), 1);
        csr[pos] = __ldg(src + e);
    }
}

// ================= context =================
__global__ void k_lead(const float* __restrict__ lf, float* __restrict__ lead, int nl) {
    int d = threadIdx.x;
    float a0 = 0.f, a1 = 0.f, a2 = 0.f, a3 = 0.f;
    int r = 0;
    for (; r + 3 < nl; r += 4) {
        a0 += lf[(r + 0) * D + d];
        a1 += lf[(r + 1) * D + d];
        a2 += lf[(r + 2) * D + d];
        a3 += lf[(r + 3) * D + d];
    }
    for (; r < nl; r++) a0 += lf[r * D + d];
    lead[d] = (a0 + a1) + (a2 + a3);
}
// ctx[i] = lead broadcast; hg[i] = 0  (one pass)
__global__ void k_initctx(float* __restrict__ ctx, float* __restrict__ hg,
                          const float* __restrict__ lead, int n) {
    int i = blockIdx.x * blockDim.x + threadIdx.x;
    if (i < n) { ctx[i] = lead[i & (D - 1)]; hg[i] = 0.f; }
}
__global__ void k_scatter_rows(const float4* __restrict__ rows, const int* __restrict__ ids,
                               float* __restrict__ out, int n) {
    int t = blockIdx.x * blockDim.x + threadIdx.x;
    int r = t >> 5, lane = t & 31;
    if (r >= n) return;
    int g = __ldg(ids + r);
    float4 v = __ldg(rows + (size_t)r * 32 + lane);
    red4(out + (size_t)g * D + lane * 4, v);
}
// pg[g] = hg[g]@W + ctx[g]@Wc + b; also zero hgNext[g]
__global__ void k_pg(const float* __restrict__ hg, const float* __restrict__ ctx,
                     const float* __restrict__ W, const float* __restrict__ Wc,
                     const float* __restrict__ b, float* __restrict__ pg,
                     float* __restrict__ hgNext) {
    int g = blockIdx.x, d = threadIdx.x;
    __shared__ float sh[D], sc[D];
    sh[d] = hg[g * D + d];
    sc[d] = ctx[g * D + d];
    __syncthreads();
    float acc = __ldg(b + d);
    #pragma unroll 8
    for (int k = 0; k < D; k++) {
        acc += sh[k] * __ldg(W + k * D + d);
        acc += sc[k] * __ldg(Wc + k * D + d);
    }
    pg[g * D + d] = acc;
    hgNext[g * D + d] = 0.f;
}
__global__ void k_fc(const float* __restrict__ in, const float* __restrict__ Wm,
                     const float* __restrict__ bias, float* __restrict__ out, int do_relu) {
    int g = blockIdx.x, d = threadIdx.x;
    __shared__ float s[D];
    s[d] = in[g * D + d];
    __syncthreads();
    float acc = __ldg(bias + d);
    #pragma unroll 8
    for (int k = 0; k < D; k++) acc += s[k] * __ldg(Wm + k * D + d);
    if (do_relu) acc = fmaxf(acc, 0.f);
    out[g * D + d] = acc;
}

// ================= fused layer: gather + GEMM + epilogue =================
// Hout = relu( ((1+eps)h + sum_nbrs h) @ W + pg[gid] ); hgOut += segsum(Hout)
#define SMEM_GEMM ((128 * 132 + 128 * 128) * 4)
__global__ void __launch_bounds__(256, 1)
k_layer(const float4* __restrict__ h4, const int* __restrict__ rowptr,
        const int* __restrict__ csr, const float4* __restrict__ Wl4,
        const float* __restrict__ pgv, const int* __restrict__ gid,
        const float* __restrict__ epsArr, int l,
        float4* __restrict__ Hout4, float* __restrict__ hgOut, int nRows) {
    extern __shared__ float smem[];
    float* As = smem;              // [128][132]  (m x k)
    float* Bs = smem + 128 * 132;  // [128][128]  (k x n)
    const int tid = threadIdx.x;
    const int m0 = blockIdx.x * 128;
    const int lane = tid & 31, w = tid >> 5;

    // load W tile
    float4* Bs4 = (float4*)Bs;
    #pragma unroll
    for (int i = 0; i < 16; i++) {
        int li = tid + i * 256;
        Bs4[li] = __ldg(Wl4 + li);
    }

    // fused gather: warp w handles rows w*16 .. w*16+15; lane = float4 chunk of the row
    const float sc = 1.0f + __ldg(epsArr + l);
    #pragma unroll 1
    for (int j = 0; j < 16; j++) {
        int m = w * 16 + j;
        int v = m0 + m;
        float4 acc = make_float4(0.f, 0.f, 0.f, 0.f);
        if (v < nRows) {
            float4 hv = __ldg(h4 + (size_t)v * 32 + lane);
            acc.x = sc * hv.x; acc.y = sc * hv.y; acc.z = sc * hv.z; acc.w = sc * hv.w;
            int beg = __ldg(rowptr + v), end = __ldg(rowptr + v + 1);
            int i = beg;
            for (; i + 3 < end; i += 4) {
                int u0 = __ldg(csr + i), u1 = __ldg(csr + i + 1);
                int u2 = __ldg(csr + i + 2), u3 = __ldg(csr + i + 3);
                float4 a = __ldg(h4 + (size_t)u0 * 32 + lane);
                float4 bq = __ldg(h4 + (size_t)u1 * 32 + lane);
                float4 cq = __ldg(h4 + (size_t)u2 * 32 + lane);
                float4 dq = __ldg(h4 + (size_t)u3 * 32 + lane);
                acc.x += (a.x + bq.x) + (cq.x + dq.x);
                acc.y += (a.y + bq.y) + (cq.y + dq.y);
                acc.z += (a.z + bq.z) + (cq.z + dq.z);
                acc.w += (a.w + bq.w) + (cq.w + dq.w);
            }
            for (; i < end; i++) {
                int u0 = __ldg(csr + i);
                float4 a = __ldg(h4 + (size_t)u0 * 32 + lane);
                acc.x += a.x; acc.y += a.y; acc.z += a.z; acc.w += a.w;
            }
        }
        *(float4*)(As + m * 132 + lane * 4) = acc;
    }
    __syncthreads();

    // mainloop: k4-chunked, A as float4
    const int tx = tid & 15, ty = tid >> 4;
    unsigned long long acc[8][4];
    #pragma unroll
    for (int i = 0; i < 8; i++)
        #pragma unroll
        for (int j = 0; j < 4; j++) acc[i][j] = 0ull;

    const float* a0p = As + (ty * 4) * 132;
    const float* a1p = As + (64 + ty * 4) * 132;

    #pragma unroll 4
    for (int k4 = 0; k4 < 32; k4++) {
        const int kb = k4 * 4;
        float4 A0[4], A1[4];
        #pragma unroll
        for (int i = 0; i < 4; i++) {
            A0[i] = *(const float4*)(a0p + i * 132 + kb);
            A1[i] = *(const float4*)(a1p + i * 132 + kb);
        }
        #pragma unroll
        for (int c = 0; c < 4; c++) {
            int k = kb + c;
            float4 b0 = *(const float4*)(Bs + k * 128 + tx * 4);
            float4 b1 = *(const float4*)(Bs + k * 128 + 64 + tx * 4);
            unsigned long long bb0 = pack2(b0.x, b0.y), bb1 = pack2(b0.z, b0.w);
            unsigned long long bb2 = pack2(b1.x, b1.y), bb3 = pack2(b1.z, b1.w);
            #pragma unroll
            for (int i = 0; i < 4; i++) {
                float a = (c == 0) ? A0[i].x : (c == 1) ? A0[i].y : (c == 2) ? A0[i].z : A0[i].w;
                unsigned long long aa = pack2(a, a);
                fma2(acc[i][0], aa, bb0);
                fma2(acc[i][1], aa, bb1);
                fma2(acc[i][2], aa, bb2);
                fma2(acc[i][3], aa, bb3);
            }
            #pragma unroll
            for (int i = 0; i < 4; i++) {
                float a = (c == 0) ? A1[i].x : (c == 1) ? A1[i].y : (c == 2) ? A1[i].z : A1[i].w;
                unsigned long long aa = pack2(a, a);
                fma2(acc[4 + i][0], aa, bb0);
                fma2(acc[4 + i][1], aa, bb1);
                fma2(acc[4 + i][2], aa, bb2);
                fma2(acc[4 + i][3], aa, bb3);
            }
        }
    }

    // epilogue: + pg[gid], relu, store, segment-sum via red4
    #pragma unroll
    for (int i = 0; i < 8; i++) {
        int m = (i < 4) ? (ty * 4 + i) : (64 + ty * 4 + i - 4);
        int mg = m0 + m;
        if (mg >= nRows) continue;
        int g = __ldg(gid + mg);
        const float4* pgr = (const float4*)(pgv + (size_t)g * D);
        float4 p0 = __ldg(pgr + tx);
        float4 p1 = __ldg(pgr + 16 + tx);
        float2 t0 = unpack2(acc[i][0]), t1 = unpack2(acc[i][1]);
        float2 t2 = unpack2(acc[i][2]), t3 = unpack2(acc[i][3]);
        float4 o0 = make_float4(fmaxf(t0.x + p0.x, 0.f), fmaxf(t0.y + p0.y, 0.f),
                                fmaxf(t1.x + p0.z, 0.f), fmaxf(t1.y + p0.w, 0.f));
        float4 o1 = make_float4(fmaxf(t2.x + p1.x, 0.f), fmaxf(t2.y + p1.y, 0.f),
                                fmaxf(t3.x + p1.z, 0.f), fmaxf(t3.y + p1.w, 0.f));
        Hout4[(size_t)mg * 32 + tx] = o0;
        Hout4[(size_t)mg * 32 + 16 + tx] = o1;
        red4(hgOut + (size_t)g * D + tx * 4, o0);
        red4(hgOut + (size_t)g * D + 64 + tx * 4, o1);
    }
}

extern "C" void kernel_launch(void* const* d_in, const int* in_sizes, int n_in,
                              void* d_out, int out_size) {
    const float* x        = (const float*)d_in[0];
    const int*   src      = (const int*)d_in[1];
    const int*   dst      = (const int*)d_in[2];
    const int*   gids     = (const int*)d_in[3];
    const float* initf    = (const float*)d_in[4];
    const int*   init_ids = (const int*)d_in[5];
    const float* leadf    = (const float*)d_in[6];
    const float* W        = (const float*)d_in[7];
    const float* Wc       = (const float*)d_in[8];
    const float* b        = (const float*)d_in[9];
    const float* eps      = (const float*)d_in[10];
    const float* fc1_w    = (const float*)d_in[11];
    const float* fc1_b    = (const float*)d_in[12];
    const float* fc2_w    = (const float*)d_in[13];
    const float* fc2_b    = (const float*)d_in[14];

    const int N  = in_sizes[0] / D;
    const int E  = in_sizes[1];
    const int NI = in_sizes[4] / D;
    const int NL = in_sizes[6] / D;
    const int L  = in_sizes[10];
    const int G  = out_size / D;

    float *h0, *h1, *hgA, *hgB, *ctx, *pg, *tbuf, *lead;
    int *rowptr, *cursor, *csr, *bsum;
    cudaGetSymbolAddress((void**)&h0, g_h0);
    cudaGetSymbolAddress((void**)&h1, g_h1);
    cudaGetSymbolAddress((void**)&hgA, g_hgA);
    cudaGetSymbolAddress((void**)&hgB, g_hgB);
    cudaGetSymbolAddress((void**)&ctx, g_ctx);
    cudaGetSymbolAddress((void**)&pg, g_pg);
    cudaGetSymbolAddress((void**)&tbuf, g_t);
    cudaGetSymbolAddress((void**)&lead, g_lead);
    cudaGetSymbolAddress((void**)&rowptr, g_rowptr);
    cudaGetSymbolAddress((void**)&cursor, g_cursor);
    cudaGetSymbolAddress((void**)&csr, g_csr);
    cudaGetSymbolAddress((void**)&bsum, g_bsum);

    cudaFuncSetAttribute(k_layer, cudaFuncAttributeMaxDynamicSharedMemorySize, SMEM_GEMM);

    const int NB = (N + 1023) / 1024;

    // CSR build
    k_zeroi<<<(N + 255) / 256, 256>>>(cursor, N);
    k_hist<<<(E + 255) / 256, 256>>>(dst, cursor, E);
    k_bsum<<<NB, 256>>>(cursor, bsum, N);
    k_scanblk<<<1, 256>>>(bsum, NB, rowptr, N, E);
    k_scanfin<<<NB, 256>>>(cursor, bsum, rowptr, cursor, N);
    k_fill<<<(E + 255) / 256, 256>>>(src, dst, cursor, csr, E);

    // context
    k_lead<<<1, D>>>(leadf, lead, NL);
    k_initctx<<<(G * D + 255) / 256, 256>>>(ctx, hgA, lead, G * D);
    k_scatter_rows<<<(N * 32 + 255) / 256, 256>>>((const float4*)x, gids, hgA, N);
    k_scatter_rows<<<(NI * 32 + 255) / 256, 256>>>((const float4*)initf, init_ids, ctx, NI);

    const float* hin = x;
    float* hbuf[2] = {h0, h1};
    float* hg_in = hgA;
    float* hg_out = hgB;

    for (int l = 0; l < L; l++) {
        float* hout = hbuf[l & 1];
        k_pg<<<G, D>>>(hg_in, ctx, W + (size_t)l * D * D, Wc + (size_t)l * D * D,
                       b + l * D, pg, hg_out);
        k_layer<<<(N + 127) / 128, 256, SMEM_GEMM>>>(
            (const float4*)hin, rowptr, csr,
            (const float4*)(W + (size_t)l * D * D),
            pg, gids, eps, l, (float4*)hout, hg_out, N);
        hin = hout;
        float* tmp = hg_in; hg_in = hg_out; hg_out = tmp;
    }

    k_fc<<<G, D>>>(hg_in, fc1_w, fc1_b, tbuf, 1);
    k_fc<<<G, D>>>(tbuf, fc2_w, fc2_b, (float*)d_out, 0);
}

// round 5
// speedup vs baseline: 2.4846x; 2.4846x over previous
#include <cuda_runtime.h>
#include <cuda_bf16.h>

// GGIN: 3-layer GIN + graph readout. N=100000, E=1600000, D=128, G=1024, L=3, C=128.
// R5: revert R4's gather/GEMM fusion (occupancy collapse), keep scan/init trims.
//   layer: m[v] = (1+eps)h[v] + sum_{u in N(v)} h[u]      (warp-per-node gather, high occ)
//          h'   = relu(m @ W[l] + pg_l[gid])              (fp32x2 SIMT GEMM, 128x128 tile)
//          pg_l = hg@W + ctx@Wc + b (per-graph), hg' = segsum(h') fused in GEMM epilogue

#define D 128
#define MAXN 100000
#define MAXG 1024
#define MAXE 1600000

__device__ float g_h0[(size_t)MAXN * D];
__device__ float g_h1[(size_t)MAXN * D];
__device__ float g_m[(size_t)MAXN * D];
__device__ float g_hgA[MAXG * D];
__device__ float g_hgB[MAXG * D];
__device__ float g_ctx[MAXG * D];
__device__ float g_pg[MAXG * D];
__device__ float g_t[MAXG * D];
__device__ float g_lead[D];
__device__ int   g_rowptr[MAXN + 1];
__device__ int   g_cursor[MAXN];
__device__ int   g_csr[MAXE];
__device__ int   g_bsum[256];

__device__ __forceinline__ void red4(float* p, float4 v) {
    asm volatile("red.global.add.v4.f32 [%0], {%1,%2,%3,%4};"
                 :: "l"(p), "f"(v.x), "f"(v.y), "f"(v.z), "f"(v.w) : "memory");
}
__device__ __forceinline__ unsigned long long pack2(float x, float y) {
    unsigned long long r;
    asm("mov.b64 %0, {%1,%2};" : "=l"(r) : "f"(x), "f"(y));
    return r;
}
__device__ __forceinline__ void fma2(unsigned long long& d, unsigned long long a, unsigned long long b) {
    asm("fma.rn.f32x2 %0, %1, %2, %0;" : "+l"(d) : "l"(a), "l"(b));
}
__device__ __forceinline__ float2 unpack2(unsigned long long v) {
    float2 r;
    asm("mov.b64 {%0,%1}, %2;" : "=f"(r.x), "=f"(r.y) : "l"(v));
    return r;
}

__global__ void k_zeroi(int* __restrict__ p, int n) {
    int i = blockIdx.x * blockDim.x + threadIdx.x;
    if (i < n) p[i] = 0;
}

// ================= CSR build =================
__global__ void k_hist(const int* __restrict__ dst, int* __restrict__ deg, int nE) {
    int e = blockIdx.x * blockDim.x + threadIdx.x;
    if (e < nE) atomicAdd(deg + __ldg(dst + e), 1);
}
__global__ void k_bsum(const int* __restrict__ deg, int* __restrict__ bsum, int n) {
    __shared__ int sh[8];
    int base = blockIdx.x * 1024 + threadIdx.x * 4;
    int s = 0;
    #pragma unroll
    for (int j = 0; j < 4; j++) { int i = base + j; if (i < n) s += deg[i]; }
    #pragma unroll
    for (int o = 16; o > 0; o >>= 1) s += __shfl_down_sync(0xffffffffu, s, o);
    if ((threadIdx.x & 31) == 0) sh[threadIdx.x >> 5] = s;
    __syncthreads();
    if (threadIdx.x == 0) {
        int t = 0;
        for (int w = 0; w < 8; w++) t += sh[w];
        bsum[blockIdx.x] = t;
    }
}
__global__ void k_scanblk(int* __restrict__ bsum, int nb, int* __restrict__ rowptr, int n, int nE) {
    __shared__ int ws[8];
    __shared__ int wexc[8];
    int tid = threadIdx.x;
    int lane = tid & 31, warp = tid >> 5;
    int v = (tid < nb) ? bsum[tid] : 0;
    int p = v;
    #pragma unroll
    for (int o = 1; o < 32; o <<= 1) {
        int t = __shfl_up_sync(0xffffffffu, p, o);
        if (lane >= o) p += t;
    }
    if (lane == 31) ws[warp] = p;
    __syncthreads();
    if (tid == 0) {
        int acc = 0;
        #pragma unroll
        for (int w = 0; w < 8; w++) { wexc[w] = acc; acc += ws[w]; }
        rowptr[n] = nE;
    }
    __syncthreads();
    if (tid < nb) bsum[tid] = p - v + wexc[warp];
}
__global__ void k_scanfin(int* __restrict__ deg, const int* __restrict__ bsum,
                          int* __restrict__ rowptr, int* __restrict__ cursor, int n) {
    __shared__ int wsum[8];
    __shared__ int wexc[8];
    int lane = threadIdx.x & 31, warp = threadIdx.x >> 5;
    int base = blockIdx.x * 1024 + threadIdx.x * 4;
    int v[4]; int s = 0;
    #pragma unroll
    for (int j = 0; j < 4; j++) { int i = base + j; v[j] = (i < n) ? deg[i] : 0; s += v[j]; }
    int pre = s;
    #pragma unroll
    for (int o = 1; o < 32; o <<= 1) {
        int t = __shfl_up_sync(0xffffffffu, pre, o);
        if (lane >= o) pre += t;
    }
    int excl = pre - s;
    if (lane == 31) wsum[warp] = pre;
    __syncthreads();
    if (threadIdx.x == 0) {
        int acc = 0;
        #pragma unroll
        for (int w = 0; w < 8; w++) { wexc[w] = acc; acc += wsum[w]; }
    }
    __syncthreads();
    int off = bsum[blockIdx.x] + wexc[warp] + excl;
    #pragma unroll
    for (int j = 0; j < 4; j++) {
        int i = base + j;
        if (i < n) { rowptr[i] = off; cursor[i] = off; off += v[j]; }
    }
}
__global__ void k_fill(const int* __restrict__ src, const int* __restrict__ dst,
                       int* __restrict__ cursor, int* __restrict__ csr, int nE) {
    int e = blockIdx.x * blockDim.x + threadIdx.x;
    if (e < nE) {
        int pos = atomicAdd(cursor + __ldg(dst + e), 1);
        csr[pos] = __ldg(src + e);
    }
}

// ================= context =================
__global__ void k_lead(const float* __restrict__ lf, float* __restrict__ lead, int nl) {
    int d = threadIdx.x;
    float a0 = 0.f, a1 = 0.f, a2 = 0.f, a3 = 0.f;
    int r = 0;
    for (; r + 3 < nl; r += 4) {
        a0 += lf[(r + 0) * D + d];
        a1 += lf[(r + 1) * D + d];
        a2 += lf[(r + 2) * D + d];
        a3 += lf[(r + 3) * D + d];
    }
    for (; r < nl; r++) a0 += lf[r * D + d];
    lead[d] = (a0 + a1) + (a2 + a3);
}
__global__ void k_initctx(float* __restrict__ ctx, float* __restrict__ hg,
                          const float* __restrict__ lead, int n) {
    int i = blockIdx.x * blockDim.x + threadIdx.x;
    if (i < n) { ctx[i] = lead[i & (D - 1)]; hg[i] = 0.f; }
}
__global__ void k_scatter_rows(const float4* __restrict__ rows, const int* __restrict__ ids,
                               float* __restrict__ out, int n) {
    int t = blockIdx.x * blockDim.x + threadIdx.x;
    int r = t >> 5, lane = t & 31;
    if (r >= n) return;
    int g = __ldg(ids + r);
    float4 v = __ldg(rows + (size_t)r * 32 + lane);
    red4(out + (size_t)g * D + lane * 4, v);
}
__global__ void k_pg(const float* __restrict__ hg, const float* __restrict__ ctx,
                     const float* __restrict__ W, const float* __restrict__ Wc,
                     const float* __restrict__ b, float* __restrict__ pg,
                     float* __restrict__ hgNext) {
    int g = blockIdx.x, d = threadIdx.x;
    __shared__ float sh[D], sc[D];
    sh[d] = hg[g * D + d];
    sc[d] = ctx[g * D + d];
    __syncthreads();
    float acc = __ldg(b + d);
    #pragma unroll 8
    for (int k = 0; k < D; k++) {
        acc += sh[k] * __ldg(W + k * D + d);
        acc += sc[k] * __ldg(Wc + k * D + d);
    }
    pg[g * D + d] = acc;
    hgNext[g * D + d] = 0.f;
}
__global__ void k_fc(const float* __restrict__ in, const float* __restrict__ Wm,
                     const float* __restrict__ bias, float* __restrict__ out, int do_relu) {
    int g = blockIdx.x, d = threadIdx.x;
    __shared__ float s[D];
    s[d] = in[g * D + d];
    __syncthreads();
    float acc = __ldg(bias + d);
    #pragma unroll 8
    for (int k = 0; k < D; k++) acc += s[k] * __ldg(Wm + k * D + d);
    if (do_relu) acc = fmaxf(acc, 0.f);
    out[g * D + d] = acc;
}

// ================= gather: m[v] = (1+eps)h[v] + sum h[u] (warp per node) ==========
__global__ void k_gather(const float4* __restrict__ h4, const int* __restrict__ rowptr,
                         const int* __restrict__ csr, float4* __restrict__ m4,
                         const float* __restrict__ epsArr, int l, int n) {
    int t = blockIdx.x * blockDim.x + threadIdx.x;
    int v = t >> 5, lane = t & 31;
    if (v >= n) return;
    const float sc = 1.0f + __ldg(epsArr + l);
    int beg = __ldg(rowptr + v), end = __ldg(rowptr + v + 1);
    float4 hv = __ldg(h4 + (size_t)v * 32 + lane);
    float4 acc = make_float4(sc * hv.x, sc * hv.y, sc * hv.z, sc * hv.w);
    int i = beg;
    for (; i + 3 < end; i += 4) {
        int u0 = __ldg(csr + i), u1 = __ldg(csr + i + 1);
        int u2 = __ldg(csr + i + 2), u3 = __ldg(csr + i + 3);
        float4 a = __ldg(h4 + (size_t)u0 * 32 + lane);
        float4 bq = __ldg(h4 + (size_t)u1 * 32 + lane);
        float4 cq = __ldg(h4 + (size_t)u2 * 32 + lane);
        float4 dq = __ldg(h4 + (size_t)u3 * 32 + lane);
        acc.x += (a.x + bq.x) + (cq.x + dq.x);
        acc.y += (a.y + bq.y) + (cq.y + dq.y);
        acc.z += (a.z + bq.z) + (cq.z + dq.z);
        acc.w += (a.w + bq.w) + (cq.w + dq.w);
    }
    for (; i < end; i++) {
        int u0 = __ldg(csr + i);
        float4 a = __ldg(h4 + (size_t)u0 * 32 + lane);
        acc.x += a.x; acc.y += a.y; acc.z += a.z; acc.w += a.w;
    }
    m4[(size_t)v * 32 + lane] = acc;
}

// ================= node GEMM (R3-proven mainloop) =================
#define SMEM_GEMM ((128 * 132 + 128 * 128) * 4)
__global__ void __launch_bounds__(256, 1)
k_gemm(const float4* __restrict__ M4, const float4* __restrict__ Wl4,
       const float* __restrict__ pgv, const int* __restrict__ gid,
       float4* __restrict__ Hout4, float* __restrict__ hgOut, int nRows) {
    extern __shared__ float smem[];
    float* As = smem;              // [128][132]
    float* Bs = smem + 128 * 132;  // [128][128]
    const int tid = threadIdx.x;
    const int m0 = blockIdx.x * 128;

    float4* Bs4 = (float4*)Bs;
    #pragma unroll
    for (int i = 0; i < 16; i++) {
        int li = tid + i * 256;
        Bs4[li] = __ldg(Wl4 + li);
    }
    #pragma unroll
    for (int i = 0; i < 16; i++) {
        int li = tid + i * 256;
        int m = li >> 5, k4 = li & 31;
        int mg = m0 + m;
        float4 v = (mg < nRows) ? __ldg(M4 + (size_t)mg * 32 + k4)
                                : make_float4(0.f, 0.f, 0.f, 0.f);
        *(float4*)(As + m * 132 + k4 * 4) = v;
    }
    __syncthreads();

    const int tx = tid & 15, ty = tid >> 4;
    unsigned long long acc[8][4];
    #pragma unroll
    for (int i = 0; i < 8; i++)
        #pragma unroll
        for (int j = 0; j < 4; j++) acc[i][j] = 0ull;

    const float* a0 = As + (ty * 4) * 132;
    const float* a1 = As + (64 + ty * 4) * 132;

    #pragma unroll 8
    for (int k = 0; k < 128; k++) {
        float4 b0 = *(const float4*)(Bs + k * 128 + tx * 4);
        float4 b1 = *(const float4*)(Bs + k * 128 + 64 + tx * 4);
        unsigned long long bb0 = pack2(b0.x, b0.y), bb1 = pack2(b0.z, b0.w);
        unsigned long long bb2 = pack2(b1.x, b1.y), bb3 = pack2(b1.z, b1.w);
        #pragma unroll
        for (int i = 0; i < 4; i++) {
            float a = a0[i * 132 + k];
            unsigned long long aa = pack2(a, a);
            fma2(acc[i][0], aa, bb0);
            fma2(acc[i][1], aa, bb1);
            fma2(acc[i][2], aa, bb2);
            fma2(acc[i][3], aa, bb3);
        }
        #pragma unroll
        for (int i = 0; i < 4; i++) {
            float a = a1[i * 132 + k];
            unsigned long long aa = pack2(a, a);
            fma2(acc[4 + i][0], aa, bb0);
            fma2(acc[4 + i][1], aa, bb1);
            fma2(acc[4 + i][2], aa, bb2);
            fma2(acc[4 + i][3], aa, bb3);
        }
    }

    #pragma unroll
    for (int i = 0; i < 8; i++) {
        int m = (i < 4) ? (ty * 4 + i) : (64 + ty * 4 + i - 4);
        int mg = m0 + m;
        if (mg >= nRows) continue;
        int g = __ldg(gid + mg);
        const float4* pgr = (const float4*)(pgv + (size_t)g * D);
        float4 p0 = __ldg(pgr + tx);
        float4 p1 = __ldg(pgr + 16 + tx);
        float2 t0 = unpack2(acc[i][0]), t1 = unpack2(acc[i][1]);
        float2 t2 = unpack2(acc[i][2]), t3 = unpack2(acc[i][3]);
        float4 o0 = make_float4(fmaxf(t0.x + p0.x, 0.f), fmaxf(t0.y + p0.y, 0.f),
                                fmaxf(t1.x + p0.z, 0.f), fmaxf(t1.y + p0.w, 0.f));
        float4 o1 = make_float4(fmaxf(t2.x + p1.x, 0.f), fmaxf(t2.y + p1.y, 0.f),
                                fmaxf(t3.x + p1.z, 0.f), fmaxf(t3.y + p1.w, 0.f));
        Hout4[(size_t)mg * 32 + tx] = o0;
        Hout4[(size_t)mg * 32 + 16 + tx] = o1;
        red4(hgOut + (size_t)g * D + tx * 4, o0);
        red4(hgOut + (size_t)g * D + 64 + tx * 4, o1);
    }
}

extern "C" void kernel_launch(void* const* d_in, const int* in_sizes, int n_in,
                              void* d_out, int out_size) {
    const float* x        = (const float*)d_in[0];
    const int*   src      = (const int*)d_in[1];
    const int*   dst      = (const int*)d_in[2];
    const int*   gids     = (const int*)d_in[3];
    const float* initf    = (const float*)d_in[4];
    const int*   init_ids = (const int*)d_in[5];
    const float* leadf    = (const float*)d_in[6];
    const float* W        = (const float*)d_in[7];
    const float* Wc       = (const float*)d_in[8];
    const float* b        = (const float*)d_in[9];
    const float* eps      = (const float*)d_in[10];
    const float* fc1_w    = (const float*)d_in[11];
    const float* fc1_b    = (const float*)d_in[12];
    const float* fc2_w    = (const float*)d_in[13];
    const float* fc2_b    = (const float*)d_in[14];

    const int N  = in_sizes[0] / D;
    const int E  = in_sizes[1];
    const int NI = in_sizes[4] / D;
    const int NL = in_sizes[6] / D;
    const int L  = in_sizes[10];
    const int G  = out_size / D;

    float *h0, *h1, *mbuf, *hgA, *hgB, *ctx, *pg, *tbuf, *lead;
    int *rowptr, *cursor, *csr, *bsum;
    cudaGetSymbolAddress((void**)&h0, g_h0);
    cudaGetSymbolAddress((void**)&h1, g_h1);
    cudaGetSymbolAddress((void**)&mbuf, g_m);
    cudaGetSymbolAddress((void**)&hgA, g_hgA);
    cudaGetSymbolAddress((void**)&hgB, g_hgB);
    cudaGetSymbolAddress((void**)&ctx, g_ctx);
    cudaGetSymbolAddress((void**)&pg, g_pg);
    cudaGetSymbolAddress((void**)&tbuf, g_t);
    cudaGetSymbolAddress((void**)&lead, g_lead);
    cudaGetSymbolAddress((void**)&rowptr, g_rowptr);
    cudaGetSymbolAddress((void**)&cursor, g_cursor);
    cudaGetSymbolAddress((void**)&csr, g_csr);
    cudaGetSymbolAddress((void**)&bsum, g_bsum);

    cudaFuncSetAttribute(k_gemm, cudaFuncAttributeMaxDynamicSharedMemorySize, SMEM_GEMM);

    const int NB = (N + 1023) / 1024;

    // CSR build
    k_zeroi<<<(N + 255) / 256, 256>>>(cursor, N);
    k_hist<<<(E + 255) / 256, 256>>>(dst, cursor, E);
    k_bsum<<<NB, 256>>>(cursor, bsum, N);
    k_scanblk<<<1, 256>>>(bsum, NB, rowptr, N, E);
    k_scanfin<<<NB, 256>>>(cursor, bsum, rowptr, cursor, N);
    k_fill<<<(E + 255) / 256, 256>>>(src, dst, cursor, csr, E);

    // context
    k_lead<<<1, D>>>(leadf, lead, NL);
    k_initctx<<<(G * D + 255) / 256, 256>>>(ctx, hgA, lead, G * D);
    k_scatter_rows<<<(N * 32 + 255) / 256, 256>>>((const float4*)x, gids, hgA, N);
    k_scatter_rows<<<(NI * 32 + 255) / 256, 256>>>((const float4*)initf, init_ids, ctx, NI);

    const float* hin = x;
    float* hbuf[2] = {h0, h1};
    float* hg_in = hgA;
    float* hg_out = hgB;

    for (int l = 0; l < L; l++) {
        float* hout = hbuf[l & 1];
        k_gather<<<(N * 32 + 255) / 256, 256>>>((const float4*)hin, rowptr, csr,
                                                (float4*)mbuf, eps, l, N);
        k_pg<<<G, D>>>(hg_in, ctx, W + (size_t)l * D * D, Wc + (size_t)l * D * D,
                       b + l * D, pg, hg_out);
        k_gemm<<<(N + 127) / 128, 256, SMEM_GEMM>>>(
            (const float4*)mbuf, (const float4*)(W + (size_t)l * D * D),
            pg, gids, (float4*)hout, hg_out, N);
        hin = hout;
        float* tmp = hg_in; hg_in = hg_out; hg_out = tmp;
    }

    k_fc<<<G, D>>>(hg_in, fc1_w, fc1_b, tbuf, 1);
    k_fc<<<G, D>>>(tbuf, fc2_w, fc2_b, (float*)d_out, 0);
}

// round 9
// speedup vs baseline: 2.5320x; 1.0191x over previous
#include <cuda_runtime.h>
#include <cuda_fp16.h>
#include <cstdint>

// GGIN: 3-layer GIN + graph readout. N=100000, E=1600000, D=128, G=1024, L=3, C=128.
// R9: h stored fp16 (halves edge-gather read traffic); m and ALL accumulation fp32.
//     R8 failed from fp16 OVERFLOW of m (|m| ~ 1e5 at layer 3) — m stays fp32 here.
//     Final layer's node output is never read -> skip its store entirely.

#define D 128
#define MAXN 100000
#define MAXG 1024
#define MAXE 1600000

// fp16 h buffers: one row = 128 halves = 32 x uint2 (8B per lane)
__device__ uint2 g_xh[(size_t)MAXN * 32];
__device__ uint2 g_h0h[(size_t)MAXN * 32];
__device__ uint2 g_h1h[(size_t)MAXN * 32];
__device__ float g_m[(size_t)MAXN * D];      // fp32 m (range!)
__device__ float g_hgA[MAXG * D];
__device__ float g_hgB[MAXG * D];
__device__ float g_ctx[MAXG * D];
__device__ float g_pg[MAXG * D];
__device__ float g_t[MAXG * D];
__device__ float g_lead[D];
__device__ int   g_rowptr[MAXN + 1];
__device__ int   g_cursor[MAXN];
__device__ int   g_csr[MAXE];
__device__ int   g_bsum[256];

__device__ __forceinline__ void red4(float* p, float4 v) {
    asm volatile("red.global.add.v4.f32 [%0], {%1,%2,%3,%4};"
                 :: "l"(p), "f"(v.x), "f"(v.y), "f"(v.z), "f"(v.w) : "memory");
}
__device__ __forceinline__ unsigned long long pack2(float x, float y) {
    unsigned long long r;
    asm("mov.b64 %0, {%1,%2};" : "=l"(r) : "f"(x), "f"(y));
    return r;
}
__device__ __forceinline__ void fma2(unsigned long long& d, unsigned long long a, unsigned long long b) {
    asm("fma.rn.f32x2 %0, %1, %2, %0;" : "+l"(d) : "l"(a), "l"(b));
}
__device__ __forceinline__ float2 unpack2(unsigned long long v) {
    float2 r;
    asm("mov.b64 {%0,%1}, %2;" : "=f"(r.x), "=f"(r.y) : "l"(v));
    return r;
}
__device__ __forceinline__ float4 h2f4(uint2 u) {
    __half2 a = *(__half2*)&u.x, b = *(__half2*)&u.y;
    float2 fa = __half22float2(a), fb = __half22float2(b);
    return make_float4(fa.x, fa.y, fb.x, fb.y);
}
__device__ __forceinline__ uint2 f42h(float4 v) {
    __half2 a = __floats2half2_rn(v.x, v.y);
    __half2 b = __floats2half2_rn(v.z, v.w);
    uint2 u;
    u.x = *(uint32_t*)&a;
    u.y = *(uint32_t*)&b;
    return u;
}

__global__ void k_zeroi(int* __restrict__ p, int n) {
    int i = blockIdx.x * blockDim.x + threadIdx.x;
    if (i < n) p[i] = 0;
}
__global__ void k_tohalf(const float4* __restrict__ x4, uint2* __restrict__ out, int n4) {
    int i = blockIdx.x * blockDim.x + threadIdx.x;
    if (i < n4) out[i] = f42h(__ldg(x4 + i));
}

// ================= CSR build =================
__global__ void k_hist(const int* __restrict__ dst, int* __restrict__ deg, int nE) {
    int e = blockIdx.x * blockDim.x + threadIdx.x;
    if (e < nE) atomicAdd(deg + __ldg(dst + e), 1);
}
__global__ void k_bsum(const int* __restrict__ deg, int* __restrict__ bsum, int n) {
    __shared__ int sh[8];
    int base = blockIdx.x * 1024 + threadIdx.x * 4;
    int s = 0;
    #pragma unroll
    for (int j = 0; j < 4; j++) { int i = base + j; if (i < n) s += deg[i]; }
    #pragma unroll
    for (int o = 16; o > 0; o >>= 1) s += __shfl_down_sync(0xffffffffu, s, o);
    if ((threadIdx.x & 31) == 0) sh[threadIdx.x >> 5] = s;
    __syncthreads();
    if (threadIdx.x == 0) {
        int t = 0;
        for (int w = 0; w < 8; w++) t += sh[w];
        bsum[blockIdx.x] = t;
    }
}
__global__ void k_scanblk(int* __restrict__ bsum, int nb, int* __restrict__ rowptr, int n, int nE) {
    __shared__ int ws[8];
    __shared__ int wexc[8];
    int tid = threadIdx.x;
    int lane = tid & 31, warp = tid >> 5;
    int v = (tid < nb) ? bsum[tid] : 0;
    int p = v;
    #pragma unroll
    for (int o = 1; o < 32; o <<= 1) {
        int t = __shfl_up_sync(0xffffffffu, p, o);
        if (lane >= o) p += t;
    }
    if (lane == 31) ws[warp] = p;
    __syncthreads();
    if (tid == 0) {
        int acc = 0;
        #pragma unroll
        for (int w = 0; w < 8; w++) { wexc[w] = acc; acc += ws[w]; }
        rowptr[n] = nE;
    }
    __syncthreads();
    if (tid < nb) bsum[tid] = p - v + wexc[warp];
}
__global__ void k_scanfin(int* __restrict__ deg, const int* __restrict__ bsum,
                          int* __restrict__ rowptr, int* __restrict__ cursor, int n) {
    __shared__ int wsum[8];
    __shared__ int wexc[8];
    int lane = threadIdx.x & 31, warp = threadIdx.x >> 5;
    int base = blockIdx.x * 1024 + threadIdx.x * 4;
    int v[4]; int s = 0;
    #pragma unroll
    for (int j = 0; j < 4; j++) { int i = base + j; v[j] = (i < n) ? deg[i] : 0; s += v[j]; }
    int pre = s;
    #pragma unroll
    for (int o = 1; o < 32; o <<= 1) {
        int t = __shfl_up_sync(0xffffffffu, pre, o);
        if (lane >= o) pre += t;
    }
    int excl = pre - s;
    if (lane == 31) wsum[warp] = pre;
    __syncthreads();
    if (threadIdx.x == 0) {
        int acc = 0;
        #pragma unroll
        for (int w = 0; w < 8; w++) { wexc[w] = acc; acc += wsum[w]; }
    }
    __syncthreads();
    int off = bsum[blockIdx.x] + wexc[warp] + excl;
    #pragma unroll
    for (int j = 0; j < 4; j++) {
        int i = base + j;
        if (i < n) { rowptr[i] = off; cursor[i] = off; off += v[j]; }
    }
}
__global__ void k_fill(const int* __restrict__ src, const int* __restrict__ dst,
                       int* __restrict__ cursor, int* __restrict__ csr, int nE) {
    int e = blockIdx.x * blockDim.x + threadIdx.x;
    if (e < nE) {
        int pos = atomicAdd(cursor + __ldg(dst + e), 1);
        csr[pos] = __ldg(src + e);
    }
}

// ================= context =================
__global__ void k_lead(const float* __restrict__ lf, float* __restrict__ lead, int nl) {
    int d = threadIdx.x;
    float a0 = 0.f, a1 = 0.f, a2 = 0.f, a3 = 0.f;
    int r = 0;
    for (; r + 3 < nl; r += 4) {
        a0 += lf[(r + 0) * D + d];
        a1 += lf[(r + 1) * D + d];
        a2 += lf[(r + 2) * D + d];
        a3 += lf[(r + 3) * D + d];
    }
    for (; r < nl; r++) a0 += lf[r * D + d];
    lead[d] = (a0 + a1) + (a2 + a3);
}
__global__ void k_initctx(float* __restrict__ ctx, float* __restrict__ hg,
                          const float* __restrict__ lead, int n) {
    int i = blockIdx.x * blockDim.x + threadIdx.x;
    if (i < n) { ctx[i] = lead[i & (D - 1)]; hg[i] = 0.f; }
}
__global__ void k_scatter_rows(const float4* __restrict__ rows, const int* __restrict__ ids,
                               float* __restrict__ out, int n) {
    int t = blockIdx.x * blockDim.x + threadIdx.x;
    int r = t >> 5, lane = t & 31;
    if (r >= n) return;
    int g = __ldg(ids + r);
    float4 v = __ldg(rows + (size_t)r * 32 + lane);
    red4(out + (size_t)g * D + lane * 4, v);
}
__global__ void k_pg(const float* __restrict__ hg, const float* __restrict__ ctx,
                     const float* __restrict__ W, const float* __restrict__ Wc,
                     const float* __restrict__ b, float* __restrict__ pg,
                     float* __restrict__ hgNext) {
    int g = blockIdx.x, d = threadIdx.x;
    __shared__ float sh[D], sc[D];
    sh[d] = hg[g * D + d];
    sc[d] = ctx[g * D + d];
    __syncthreads();
    float acc = __ldg(b + d);
    #pragma unroll 8
    for (int k = 0; k < D; k++) {
        acc += sh[k] * __ldg(W + k * D + d);
        acc += sc[k] * __ldg(Wc + k * D + d);
    }
    pg[g * D + d] = acc;
    hgNext[g * D + d] = 0.f;
}
__global__ void k_fc(const float* __restrict__ in, const float* __restrict__ Wm,
                     const float* __restrict__ bias, float* __restrict__ out, int do_relu) {
    int g = blockIdx.x, d = threadIdx.x;
    __shared__ float s[D];
    s[d] = in[g * D + d];
    __syncthreads();
    float acc = __ldg(bias + d);
    #pragma unroll 8
    for (int k = 0; k < D; k++) acc += s[k] * __ldg(Wm + k * D + d);
    if (do_relu) acc = fmaxf(acc, 0.f);
    out[g * D + d] = acc;
}

// ====== gather (fp16 h rows, fp32 accum, fp32 m out) ======
__global__ void k_gather_h(const uint2* __restrict__ h2, const int* __restrict__ rowptr,
                           const int* __restrict__ csr, float4* __restrict__ m4,
                           const float* __restrict__ epsArr, int l, int n) {
    int t = blockIdx.x * blockDim.x + threadIdx.x;
    int v = t >> 5, lane = t & 31;
    if (v >= n) return;
    const float sc = 1.0f + __ldg(epsArr + l);
    int beg = __ldg(rowptr + v), end = __ldg(rowptr + v + 1);
    float4 hv = h2f4(__ldg(h2 + (size_t)v * 32 + lane));
    float4 acc = make_float4(sc * hv.x, sc * hv.y, sc * hv.z, sc * hv.w);
    int i = beg;
    for (; i + 3 < end; i += 4) {
        int u0 = __ldg(csr + i), u1 = __ldg(csr + i + 1);
        int u2 = __ldg(csr + i + 2), u3 = __ldg(csr + i + 3);
        float4 a = h2f4(__ldg(h2 + (size_t)u0 * 32 + lane));
        float4 bq = h2f4(__ldg(h2 + (size_t)u1 * 32 + lane));
        float4 cq = h2f4(__ldg(h2 + (size_t)u2 * 32 + lane));
        float4 dq = h2f4(__ldg(h2 + (size_t)u3 * 32 + lane));
        acc.x += (a.x + bq.x) + (cq.x + dq.x);
        acc.y += (a.y + bq.y) + (cq.y + dq.y);
        acc.z += (a.z + bq.z) + (cq.z + dq.z);
        acc.w += (a.w + bq.w) + (cq.w + dq.w);
    }
    for (; i < end; i++) {
        int u0 = __ldg(csr + i);
        float4 a = h2f4(__ldg(h2 + (size_t)u0 * 32 + lane));
        acc.x += a.x; acc.y += a.y; acc.z += a.z; acc.w += a.w;
    }
    m4[(size_t)v * 32 + lane] = acc;
}

// ================= node GEMM (R5-proven; fp32 M in, fp16 H out, optional store) ====
#define SMEM_GEMM ((128 * 132 + 128 * 128) * 4)
__global__ void __launch_bounds__(256, 1)
k_gemm(const float4* __restrict__ M4, const float4* __restrict__ Wl4,
       const float* __restrict__ pgv, const int* __restrict__ gid,
       uint2* __restrict__ Hout2, float* __restrict__ hgOut, int nRows, int storeH) {
    extern __shared__ float smem[];
    float* As = smem;              // [128][132]
    float* Bs = smem + 128 * 132;  // [128][128]
    const int tid = threadIdx.x;
    const int m0 = blockIdx.x * 128;

    float4* Bs4 = (float4*)Bs;
    #pragma unroll
    for (int i = 0; i < 16; i++) {
        int li = tid + i * 256;
        Bs4[li] = __ldg(Wl4 + li);
    }
    #pragma unroll
    for (int i = 0; i < 16; i++) {
        int li = tid + i * 256;
        int m = li >> 5, k4 = li & 31;
        int mg = m0 + m;
        float4 v = (mg < nRows) ? __ldg(M4 + (size_t)mg * 32 + k4)
                                : make_float4(0.f, 0.f, 0.f, 0.f);
        *(float4*)(As + m * 132 + k4 * 4) = v;
    }
    __syncthreads();

    const int tx = tid & 15, ty = tid >> 4;
    unsigned long long acc[8][4];
    #pragma unroll
    for (int i = 0; i < 8; i++)
        #pragma unroll
        for (int j = 0; j < 4; j++) acc[i][j] = 0ull;

    const float* a0 = As + (ty * 4) * 132;
    const float* a1 = As + (64 + ty * 4) * 132;

    #pragma unroll 8
    for (int k = 0; k < 128; k++) {
        float4 b0 = *(const float4*)(Bs + k * 128 + tx * 4);
        float4 b1 = *(const float4*)(Bs + k * 128 + 64 + tx * 4);
        unsigned long long bb0 = pack2(b0.x, b0.y), bb1 = pack2(b0.z, b0.w);
        unsigned long long bb2 = pack2(b1.x, b1.y), bb3 = pack2(b1.z, b1.w);
        #pragma unroll
        for (int i = 0; i < 4; i++) {
            float a = a0[i * 132 + k];
            unsigned long long aa = pack2(a, a);
            fma2(acc[i][0], aa, bb0);
            fma2(acc[i][1], aa, bb1);
            fma2(acc[i][2], aa, bb2);
            fma2(acc[i][3], aa, bb3);
        }
        #pragma unroll
        for (int i = 0; i < 4; i++) {
            float a = a1[i * 132 + k];
            unsigned long long aa = pack2(a, a);
            fma2(acc[4 + i][0], aa, bb0);
            fma2(acc[4 + i][1], aa, bb1);
            fma2(acc[4 + i][2], aa, bb2);
            fma2(acc[4 + i][3], aa, bb3);
        }
    }

    #pragma unroll
    for (int i = 0; i < 8; i++) {
        int m = (i < 4) ? (ty * 4 + i) : (64 + ty * 4 + i - 4);
        int mg = m0 + m;
        if (mg >= nRows) continue;
        int g = __ldg(gid + mg);
        const float4* pgr = (const float4*)(pgv + (size_t)g * D);
        float4 p0 = __ldg(pgr + tx);
        float4 p1 = __ldg(pgr + 16 + tx);
        float2 t0 = unpack2(acc[i][0]), t1 = unpack2(acc[i][1]);
        float2 t2 = unpack2(acc[i][2]), t3 = unpack2(acc[i][3]);
        float4 o0 = make_float4(fmaxf(t0.x + p0.x, 0.f), fmaxf(t0.y + p0.y, 0.f),
                                fmaxf(t1.x + p0.z, 0.f), fmaxf(t1.y + p0.w, 0.f));
        float4 o1 = make_float4(fmaxf(t2.x + p1.x, 0.f), fmaxf(t2.y + p1.y, 0.f),
                                fmaxf(t3.x + p1.z, 0.f), fmaxf(t3.y + p1.w, 0.f));
        if (storeH) {
            Hout2[(size_t)mg * 32 + tx] = f42h(o0);
            Hout2[(size_t)mg * 32 + 16 + tx] = f42h(o1);
        }
        red4(hgOut + (size_t)g * D + tx * 4, o0);
        red4(hgOut + (size_t)g * D + 64 + tx * 4, o1);
    }
}

extern "C" void kernel_launch(void* const* d_in, const int* in_sizes, int n_in,
                              void* d_out, int out_size) {
    const float* x        = (const float*)d_in[0];
    const int*   src      = (const int*)d_in[1];
    const int*   dst      = (const int*)d_in[2];
    const int*   gids     = (const int*)d_in[3];
    const float* initf    = (const float*)d_in[4];
    const int*   init_ids = (const int*)d_in[5];
    const float* leadf    = (const float*)d_in[6];
    const float* W        = (const float*)d_in[7];
    const float* Wc       = (const float*)d_in[8];
    const float* b        = (const float*)d_in[9];
    const float* eps      = (const float*)d_in[10];
    const float* fc1_w    = (const float*)d_in[11];
    const float* fc1_b    = (const float*)d_in[12];
    const float* fc2_w    = (const float*)d_in[13];
    const float* fc2_b    = (const float*)d_in[14];

    const int N  = in_sizes[0] / D;
    const int E  = in_sizes[1];
    const int NI = in_sizes[4] / D;
    const int NL = in_sizes[6] / D;
    const int L  = in_sizes[10];
    const int G  = out_size / D;

    uint2 *xh, *h0h, *h1h;
    float *mbuf, *hgA, *hgB, *ctx, *pg, *tbuf, *lead;
    int *rowptr, *cursor, *csr, *bsum;
    cudaGetSymbolAddress((void**)&xh, g_xh);
    cudaGetSymbolAddress((void**)&h0h, g_h0h);
    cudaGetSymbolAddress((void**)&h1h, g_h1h);
    cudaGetSymbolAddress((void**)&mbuf, g_m);
    cudaGetSymbolAddress((void**)&hgA, g_hgA);
    cudaGetSymbolAddress((void**)&hgB, g_hgB);
    cudaGetSymbolAddress((void**)&ctx, g_ctx);
    cudaGetSymbolAddress((void**)&pg, g_pg);
    cudaGetSymbolAddress((void**)&tbuf, g_t);
    cudaGetSymbolAddress((void**)&lead, g_lead);
    cudaGetSymbolAddress((void**)&rowptr, g_rowptr);
    cudaGetSymbolAddress((void**)&cursor, g_cursor);
    cudaGetSymbolAddress((void**)&csr, g_csr);
    cudaGetSymbolAddress((void**)&bsum, g_bsum);

    cudaFuncSetAttribute(k_gemm, cudaFuncAttributeMaxDynamicSharedMemorySize, SMEM_GEMM);

    const int NB = (N + 1023) / 1024;

    // CSR build
    k_zeroi<<<(N + 255) / 256, 256>>>(cursor, N);
    k_hist<<<(E + 255) / 256, 256>>>(dst, cursor, E);
    k_bsum<<<NB, 256>>>(cursor, bsum, N);
    k_scanblk<<<1, 256>>>(bsum, NB, rowptr, N, E);
    k_scanfin<<<NB, 256>>>(cursor, bsum, rowptr, cursor, N);
    k_fill<<<(E + 255) / 256, 256>>>(src, dst, cursor, csr, E);

    // context + x conversion
    k_lead<<<1, D>>>(leadf, lead, NL);
    k_initctx<<<(G * D + 255) / 256, 256>>>(ctx, hgA, lead, G * D);
    k_tohalf<<<(N * 32 + 255) / 256, 256>>>((const float4*)x, xh, N * 32);
    k_scatter_rows<<<(N * 32 + 255) / 256, 256>>>((const float4*)x, gids, hgA, N);
    k_scatter_rows<<<(NI * 32 + 255) / 256, 256>>>((const float4*)initf, init_ids, ctx, NI);

    const uint2* hin = xh;
    uint2* hbuf[2] = {h0h, h1h};
    float* hg_in = hgA;
    float* hg_out = hgB;

    for (int l = 0; l < L; l++) {
        uint2* hout = hbuf[l & 1];
        int storeH = (l + 1 < L) ? 1 : 0;   // last layer's node output is never read
        k_gather_h<<<(N * 32 + 255) / 256, 256>>>(hin, rowptr, csr,
                                                  (float4*)mbuf, eps, l, N);
        k_pg<<<G, D>>>(hg_in, ctx, W + (size_t)l * D * D, Wc + (size_t)l * D * D,
                       b + l * D, pg, hg_out);
        k_gemm<<<(N + 127) / 128, 256, SMEM_GEMM>>>(
            (const float4*)mbuf, (const float4*)(W + (size_t)l * D * D),
            pg, gids, hout, hg_out, N, storeH);
        hin = hout;
        float* tmp = hg_in; hg_in = hg_out; hg_out = tmp;
    }

    k_fc<<<G, D>>>(hg_in, fc1_w, fc1_b, tbuf, 1);
    k_fc<<<G, D>>>(tbuf, fc2_w, fc2_b, (float*)d_out, 0);
}

// round 11
// speedup vs baseline: 3.1000x; 1.2243x over previous
#include <cuda_runtime.h>
#include <cuda_fp16.h>
#include <cstdint>

// GGIN: 3-layer GIN + graph readout. N=100000, E=1600000, D=128, G=1024, L=3, C=128.
// R10: node GEMM on tensor cores via legacy mma.sync.m16n8k8.tf32 (sm_80+ ISA,
//      legal on sm_103 — only tcgen05 is fenced off). Single-pass tf32, fp32 accum.
//      Gather/CSR/context = proven R9 (559us) config.

#define D 128
#define MAXN 100000
#define MAXG 1024
#define MAXE 1600000

__device__ uint2 g_xh[(size_t)MAXN * 32];
__device__ uint2 g_h0h[(size_t)MAXN * 32];
__device__ uint2 g_h1h[(size_t)MAXN * 32];
__device__ float g_m[(size_t)MAXN * D];      // fp32 m (fp16 overflows: |m|~1e5)
__device__ float g_hgA[MAXG * D];
__device__ float g_hgB[MAXG * D];
__device__ float g_ctx[MAXG * D];
__device__ float g_pg[MAXG * D];
__device__ float g_t[MAXG * D];
__device__ float g_lead[D];
__device__ int   g_rowptr[MAXN + 1];
__device__ int   g_cursor[MAXN];
__device__ int   g_csr[MAXE];
__device__ int   g_bsum[256];

__device__ __forceinline__ void red4(float* p, float4 v) {
    asm volatile("red.global.add.v4.f32 [%0], {%1,%2,%3,%4};"
                 :: "l"(p), "f"(v.x), "f"(v.y), "f"(v.z), "f"(v.w) : "memory");
}
__device__ __forceinline__ void red2(float* p, float x, float y) {
    asm volatile("red.global.add.v2.f32 [%0], {%1,%2};"
                 :: "l"(p), "f"(x), "f"(y) : "memory");
}
__device__ __forceinline__ float tf32r(float x) {
    float r;
    asm("cvt.rna.tf32.f32 %0, %1;" : "=f"(r) : "f"(x));
    return r;
}
__device__ __forceinline__ float4 h2f4(uint2 u) {
    __half2 a = *(__half2*)&u.x, b = *(__half2*)&u.y;
    float2 fa = __half22float2(a), fb = __half22float2(b);
    return make_float4(fa.x, fa.y, fb.x, fb.y);
}
__device__ __forceinline__ uint2 f42h(float4 v) {
    __half2 a = __floats2half2_rn(v.x, v.y);
    __half2 b = __floats2half2_rn(v.z, v.w);
    uint2 u;
    u.x = *(uint32_t*)&a;
    u.y = *(uint32_t*)&b;
    return u;
}
__device__ __forceinline__ void mma_tf32(float* c, const uint32_t* a, uint32_t b0, uint32_t b1) {
    asm volatile(
        "mma.sync.aligned.m16n8k8.row.col.f32.tf32.tf32.f32 "
        "{%0,%1,%2,%3}, {%4,%5,%6,%7}, {%8,%9}, {%0,%1,%2,%3};"
        : "+f"(c[0]), "+f"(c[1]), "+f"(c[2]), "+f"(c[3])
        : "r"(a[0]), "r"(a[1]), "r"(a[2]), "r"(a[3]), "r"(b0), "r"(b1));
}

__global__ void k_zeroi(int* __restrict__ p, int n) {
    int i = blockIdx.x * blockDim.x + threadIdx.x;
    if (i < n) p[i] = 0;
}
__global__ void k_tohalf(const float4* __restrict__ x4, uint2* __restrict__ out, int n4) {
    int i = blockIdx.x * blockDim.x + threadIdx.x;
    if (i < n4) out[i] = f42h(__ldg(x4 + i));
}

// ================= CSR build =================
__global__ void k_hist(const int* __restrict__ dst, int* __restrict__ deg, int nE) {
    int e = blockIdx.x * blockDim.x + threadIdx.x;
    if (e < nE) atomicAdd(deg + __ldg(dst + e), 1);
}
__global__ void k_bsum(const int* __restrict__ deg, int* __restrict__ bsum, int n) {
    __shared__ int sh[8];
    int base = blockIdx.x * 1024 + threadIdx.x * 4;
    int s = 0;
    #pragma unroll
    for (int j = 0; j < 4; j++) { int i = base + j; if (i < n) s += deg[i]; }
    #pragma unroll
    for (int o = 16; o > 0; o >>= 1) s += __shfl_down_sync(0xffffffffu, s, o);
    if ((threadIdx.x & 31) == 0) sh[threadIdx.x >> 5] = s;
    __syncthreads();
    if (threadIdx.x == 0) {
        int t = 0;
        for (int w = 0; w < 8; w++) t += sh[w];
        bsum[blockIdx.x] = t;
    }
}
__global__ void k_scanblk(int* __restrict__ bsum, int nb, int* __restrict__ rowptr, int n, int nE) {
    __shared__ int ws[8];
    __shared__ int wexc[8];
    int tid = threadIdx.x;
    int lane = tid & 31, warp = tid >> 5;
    int v = (tid < nb) ? bsum[tid] : 0;
    int p = v;
    #pragma unroll
    for (int o = 1; o < 32; o <<= 1) {
        int t = __shfl_up_sync(0xffffffffu, p, o);
        if (lane >= o) p += t;
    }
    if (lane == 31) ws[warp] = p;
    __syncthreads();
    if (tid == 0) {
        int acc = 0;
        #pragma unroll
        for (int w = 0; w < 8; w++) { wexc[w] = acc; acc += ws[w]; }
        rowptr[n] = nE;
    }
    __syncthreads();
    if (tid < nb) bsum[tid] = p - v + wexc[warp];
}
__global__ void k_scanfin(int* __restrict__ deg, const int* __restrict__ bsum,
                          int* __restrict__ rowptr, int* __restrict__ cursor, int n) {
    __shared__ int wsum[8];
    __shared__ int wexc[8];
    int lane = threadIdx.x & 31, warp = threadIdx.x >> 5;
    int base = blockIdx.x * 1024 + threadIdx.x * 4;
    int v[4]; int s = 0;
    #pragma unroll
    for (int j = 0; j < 4; j++) { int i = base + j; v[j] = (i < n) ? deg[i] : 0; s += v[j]; }
    int pre = s;
    #pragma unroll
    for (int o = 1; o < 32; o <<= 1) {
        int t = __shfl_up_sync(0xffffffffu, pre, o);
        if (lane >= o) pre += t;
    }
    int excl = pre - s;
    if (lane == 31) wsum[warp] = pre;
    __syncthreads();
    if (threadIdx.x == 0) {
        int acc = 0;
        #pragma unroll
        for (int w = 0; w < 8; w++) { wexc[w] = acc; acc += wsum[w]; }
    }
    __syncthreads();
    int off = bsum[blockIdx.x] + wexc[warp] + excl;
    #pragma unroll
    for (int j = 0; j < 4; j++) {
        int i = base + j;
        if (i < n) { rowptr[i] = off; cursor[i] = off; off += v[j]; }
    }
}
__global__ void k_fill(const int* __restrict__ src, const int* __restrict__ dst,
                       int* __restrict__ cursor, int* __restrict__ csr, int nE) {
    int e = blockIdx.x * blockDim.x + threadIdx.x;
    if (e < nE) {
        int pos = atomicAdd(cursor + __ldg(dst + e), 1);
        csr[pos] = __ldg(src + e);
    }
}

// ================= context =================
__global__ void k_lead(const float* __restrict__ lf, float* __restrict__ lead, int nl) {
    int d = threadIdx.x;
    float a0 = 0.f, a1 = 0.f, a2 = 0.f, a3 = 0.f;
    int r = 0;
    for (; r + 3 < nl; r += 4) {
        a0 += lf[(r + 0) * D + d];
        a1 += lf[(r + 1) * D + d];
        a2 += lf[(r + 2) * D + d];
        a3 += lf[(r + 3) * D + d];
    }
    for (; r < nl; r++) a0 += lf[r * D + d];
    lead[d] = (a0 + a1) + (a2 + a3);
}
__global__ void k_initctx(float* __restrict__ ctx, float* __restrict__ hg,
                          const float* __restrict__ lead, int n) {
    int i = blockIdx.x * blockDim.x + threadIdx.x;
    if (i < n) { ctx[i] = lead[i & (D - 1)]; hg[i] = 0.f; }
}
__global__ void k_scatter_rows(const float4* __restrict__ rows, const int* __restrict__ ids,
                               float* __restrict__ out, int n) {
    int t = blockIdx.x * blockDim.x + threadIdx.x;
    int r = t >> 5, lane = t & 31;
    if (r >= n) return;
    int g = __ldg(ids + r);
    float4 v = __ldg(rows + (size_t)r * 32 + lane);
    red4(out + (size_t)g * D + lane * 4, v);
}
__global__ void k_pg(const float* __restrict__ hg, const float* __restrict__ ctx,
                     const float* __restrict__ W, const float* __restrict__ Wc,
                     const float* __restrict__ b, float* __restrict__ pg,
                     float* __restrict__ hgNext) {
    int g = blockIdx.x, d = threadIdx.x;
    __shared__ float sh[D], sc[D];
    sh[d] = hg[g * D + d];
    sc[d] = ctx[g * D + d];
    __syncthreads();
    float acc = __ldg(b + d);
    #pragma unroll 8
    for (int k = 0; k < D; k++) {
        acc += sh[k] * __ldg(W + k * D + d);
        acc += sc[k] * __ldg(Wc + k * D + d);
    }
    pg[g * D + d] = acc;
    hgNext[g * D + d] = 0.f;
}
__global__ void k_fc(const float* __restrict__ in, const float* __restrict__ Wm,
                     const float* __restrict__ bias, float* __restrict__ out, int do_relu) {
    int g = blockIdx.x, d = threadIdx.x;
    __shared__ float s[D];
    s[d] = in[g * D + d];
    __syncthreads();
    float acc = __ldg(bias + d);
    #pragma unroll 8
    for (int k = 0; k < D; k++) acc += s[k] * __ldg(Wm + k * D + d);
    if (do_relu) acc = fmaxf(acc, 0.f);
    out[g * D + d] = acc;
}

// ====== gather (fp16 h rows, fp32 accum, fp32 m out) — proven R9 ======
__global__ void k_gather_h(const uint2* __restrict__ h2, const int* __restrict__ rowptr,
                           const int* __restrict__ csr, float4* __restrict__ m4,
                           const float* __restrict__ epsArr, int l, int n) {
    int t = blockIdx.x * blockDim.x + threadIdx.x;
    int v = t >> 5, lane = t & 31;
    if (v >= n) return;
    const float sc = 1.0f + __ldg(epsArr + l);
    int beg = __ldg(rowptr + v), end = __ldg(rowptr + v + 1);
    float4 hv = h2f4(__ldg(h2 + (size_t)v * 32 + lane));
    float4 acc = make_float4(sc * hv.x, sc * hv.y, sc * hv.z, sc * hv.w);
    int i = beg;
    for (; i + 3 < end; i += 4) {
        int u0 = __ldg(csr + i), u1 = __ldg(csr + i + 1);
        int u2 = __ldg(csr + i + 2), u3 = __ldg(csr + i + 3);
        float4 a = h2f4(__ldg(h2 + (size_t)u0 * 32 + lane));
        float4 bq = h2f4(__ldg(h2 + (size_t)u1 * 32 + lane));
        float4 cq = h2f4(__ldg(h2 + (size_t)u2 * 32 + lane));
        float4 dq = h2f4(__ldg(h2 + (size_t)u3 * 32 + lane));
        acc.x += (a.x + bq.x) + (cq.x + dq.x);
        acc.y += (a.y + bq.y) + (cq.y + dq.y);
        acc.z += (a.z + bq.z) + (cq.z + dq.z);
        acc.w += (a.w + bq.w) + (cq.w + dq.w);
    }
    for (; i < end; i++) {
        int u0 = __ldg(csr + i);
        float4 a = h2f4(__ldg(h2 + (size_t)u0 * 32 + lane));
        acc.x += a.x; acc.y += a.y; acc.z += a.z; acc.w += a.w;
    }
    m4[(size_t)v * 32 + lane] = acc;
}

// ================= node GEMM: mma.sync tf32 =================
// Hout = relu(M @ W + pg[gid]); hgOut += segsum(Hout).
// CTA 128x128x128, 8 warps, warp tile 32x64. A smem stride 132, B stride 136
// (both conflict-free for the m16n8k8 fragment access patterns).
#define ASTRIDE 132
#define BSTRIDE 136
#define SMEM_GEMM ((128 * ASTRIDE + 128 * BSTRIDE) * 4)
__global__ void __launch_bounds__(256, 1)
k_gemm(const float4* __restrict__ M4, const float4* __restrict__ Wl4,
       const float* __restrict__ pgv, const int* __restrict__ gid,
       uint32_t* __restrict__ HoutH, float* __restrict__ hgOut, int nRows, int storeH) {
    extern __shared__ float smem[];
    float* As = smem;                       // [128][132]  m x k (tf32 bits)
    float* Bs = smem + 128 * ASTRIDE;       // [128][136]  k x n (tf32 bits)
    const int tid = threadIdx.x;
    const int wid = tid >> 5, lane = tid & 31;
    const int m0 = blockIdx.x * 128;
    const int warpM = (wid & 3) * 32;
    const int warpN = (wid >> 2) * 64;
    const int lr = lane >> 2, lc = lane & 3;

    // prologue: A (tf32-rounded) and B = tf32(W)
    #pragma unroll
    for (int i = 0; i < 16; i++) {
        int li = tid + i * 256;
        int row = li >> 5, k4 = li & 31;
        int mg = m0 + row;
        float4 v = (mg < nRows) ? __ldg(M4 + (size_t)mg * 32 + k4)
                                : make_float4(0.f, 0.f, 0.f, 0.f);
        v.x = tf32r(v.x); v.y = tf32r(v.y); v.z = tf32r(v.z); v.w = tf32r(v.w);
        *(float4*)(As + row * ASTRIDE + k4 * 4) = v;
    }
    #pragma unroll
    for (int i = 0; i < 16; i++) {
        int li = tid + i * 256;
        int k = li >> 5, n4 = li & 31;
        float4 v = __ldg(Wl4 + k * 32 + n4);
        v.x = tf32r(v.x); v.y = tf32r(v.y); v.z = tf32r(v.z); v.w = tf32r(v.w);
        *(float4*)(Bs + k * BSTRIDE + n4 * 4) = v;
    }
    __syncthreads();

    float acc[2][8][4];
    #pragma unroll
    for (int mt = 0; mt < 2; mt++)
        #pragma unroll
        for (int j = 0; j < 8; j++)
            #pragma unroll
            for (int q = 0; q < 4; q++) acc[mt][j][q] = 0.f;

    const uint32_t* Au = (const uint32_t*)As;
    const uint32_t* Bu = (const uint32_t*)Bs;

    #pragma unroll
    for (int ks = 0; ks < 16; ks++) {
        const int kb = ks * 8;
        uint32_t a[2][4];
        #pragma unroll
        for (int mt = 0; mt < 2; mt++) {
            int r0 = warpM + mt * 16 + lr;
            a[mt][0] = Au[r0 * ASTRIDE + kb + lc];
            a[mt][1] = Au[(r0 + 8) * ASTRIDE + kb + lc];
            a[mt][2] = Au[r0 * ASTRIDE + kb + lc + 4];
            a[mt][3] = Au[(r0 + 8) * ASTRIDE + kb + lc + 4];
        }
        #pragma unroll
        for (int j = 0; j < 8; j++) {
            int nc = warpN + j * 8 + lr;
            uint32_t b0 = Bu[(kb + lc) * BSTRIDE + nc];
            uint32_t b1 = Bu[(kb + lc + 4) * BSTRIDE + nc];
            mma_tf32(acc[0][j], a[0], b0, b1);
            mma_tf32(acc[1][j], a[1], b0, b1);
        }
    }

    // epilogue: fragment rows r, r+8 per m-tile; cols warpN + j*8 + lc*2 (+1)
    #pragma unroll
    for (int mt = 0; mt < 2; mt++) {
        #pragma unroll
        for (int half = 0; half < 2; half++) {
            int mg = m0 + warpM + mt * 16 + half * 8 + lr;
            if (mg >= nRows) continue;
            int g = __ldg(gid + mg);
            const float* pgr = pgv + (size_t)g * D;
            #pragma unroll
            for (int j = 0; j < 8; j++) {
                int nc = warpN + j * 8 + lc * 2;
                float c0 = acc[mt][j][half * 2 + 0];
                float c1 = acc[mt][j][half * 2 + 1];
                float2 p = __ldg((const float2*)(pgr + nc));
                float o0 = fmaxf(c0 + p.x, 0.f);
                float o1 = fmaxf(c1 + p.y, 0.f);
                if (storeH) {
                    __half2 hv = __floats2half2_rn(o0, o1);
                    HoutH[((size_t)mg * D + nc) >> 1] = *(uint32_t*)&hv;
                }
                red2(hgOut + (size_t)g * D + nc, o0, o1);
            }
        }
    }
}

extern "C" void kernel_launch(void* const* d_in, const int* in_sizes, int n_in,
                              void* d_out, int out_size) {
    const float* x        = (const float*)d_in[0];
    const int*   src      = (const int*)d_in[1];
    const int*   dst      = (const int*)d_in[2];
    const int*   gids     = (const int*)d_in[3];
    const float* initf    = (const float*)d_in[4];
    const int*   init_ids = (const int*)d_in[5];
    const float* leadf    = (const float*)d_in[6];
    const float* W        = (const float*)d_in[7];
    const float* Wc       = (const float*)d_in[8];
    const float* b        = (const float*)d_in[9];
    const float* eps      = (const float*)d_in[10];
    const float* fc1_w    = (const float*)d_in[11];
    const float* fc1_b    = (const float*)d_in[12];
    const float* fc2_w    = (const float*)d_in[13];
    const float* fc2_b    = (const float*)d_in[14];

    const int N  = in_sizes[0] / D;
    const int E  = in_sizes[1];
    const int NI = in_sizes[4] / D;
    const int NL = in_sizes[6] / D;
    const int L  = in_sizes[10];
    const int G  = out_size / D;

    uint2 *xh, *h0h, *h1h;
    float *mbuf, *hgA, *hgB, *ctx, *pg, *tbuf, *lead;
    int *rowptr, *cursor, *csr, *bsum;
    cudaGetSymbolAddress((void**)&xh, g_xh);
    cudaGetSymbolAddress((void**)&h0h, g_h0h);
    cudaGetSymbolAddress((void**)&h1h, g_h1h);
    cudaGetSymbolAddress((void**)&mbuf, g_m);
    cudaGetSymbolAddress((void**)&hgA, g_hgA);
    cudaGetSymbolAddress((void**)&hgB, g_hgB);
    cudaGetSymbolAddress((void**)&ctx, g_ctx);
    cudaGetSymbolAddress((void**)&pg, g_pg);
    cudaGetSymbolAddress((void**)&tbuf, g_t);
    cudaGetSymbolAddress((void**)&lead, g_lead);
    cudaGetSymbolAddress((void**)&rowptr, g_rowptr);
    cudaGetSymbolAddress((void**)&cursor, g_cursor);
    cudaGetSymbolAddress((void**)&csr, g_csr);
    cudaGetSymbolAddress((void**)&bsum, g_bsum);

    cudaFuncSetAttribute(k_gemm, cudaFuncAttributeMaxDynamicSharedMemorySize, SMEM_GEMM);

    const int NB = (N + 1023) / 1024;

    // CSR build
    k_zeroi<<<(N + 255) / 256, 256>>>(cursor, N);
    k_hist<<<(E + 255) / 256, 256>>>(dst, cursor, E);
    k_bsum<<<NB, 256>>>(cursor, bsum, N);
    k_scanblk<<<1, 256>>>(bsum, NB, rowptr, N, E);
    k_scanfin<<<NB, 256>>>(cursor, bsum, rowptr, cursor, N);
    k_fill<<<(E + 255) / 256, 256>>>(src, dst, cursor, csr, E);

    // context + x conversion
    k_lead<<<1, D>>>(leadf, lead, NL);
    k_initctx<<<(G * D + 255) / 256, 256>>>(ctx, hgA, lead, G * D);
    k_tohalf<<<(N * 32 + 255) / 256, 256>>>((const float4*)x, xh, N * 32);
    k_scatter_rows<<<(N * 32 + 255) / 256, 256>>>((const float4*)x, gids, hgA, N);
    k_scatter_rows<<<(NI * 32 + 255) / 256, 256>>>((const float4*)initf, init_ids, ctx, NI);

    const uint2* hin = xh;
    uint2* hbuf[2] = {h0h, h1h};
    float* hg_in = hgA;
    float* hg_out = hgB;

    for (int l = 0; l < L; l++) {
        uint2* hout = hbuf[l & 1];
        int storeH = (l + 1 < L) ? 1 : 0;
        k_gather_h<<<(N * 32 + 255) / 256, 256>>>(hin, rowptr, csr,
                                                  (float4*)mbuf, eps, l, N);
        k_pg<<<G, D>>>(hg_in, ctx, W + (size_t)l * D * D, Wc + (size_t)l * D * D,
                       b + l * D, pg, hg_out);
        k_gemm<<<(N + 127) / 128, 256, SMEM_GEMM>>>(
            (const float4*)mbuf, (const float4*)(W + (size_t)l * D * D),
            pg, gids, (uint32_t*)hout, hg_out, N, storeH);
        hin = hout;
        float* tmp = hg_in; hg_in = hg_out; hg_out = tmp;
    }

    k_fc<<<G, D>>>(hg_in, fc1_w, fc1_b, tbuf, 1);
    k_fc<<<G, D>>>(tbuf, fc2_w, fc2_b, (float*)d_out, 0);
}

// round 12
// speedup vs baseline: 3.3049x; 1.0661x over previous
#include <cuda_runtime.h>
#include <cuda_fp16.h>
#include <cstdint>

// GGIN: 3-layer GIN + graph readout. N=100000, E=1600000, D=128, G=1024, L=3, C=128.
// R12: gather reworked to 2 nodes/warp (16 lanes x uint4 per row) — halves warp-level
//      load-instruction count (gather is issue/latency-bound, not byte-bound).
//      tohalf fused into the x scatter. GEMM = proven R11 mma.sync tf32.

#define D 128
#define MAXN 100000
#define MAXG 1024
#define MAXE 1600000

__device__ uint2 g_xh[(size_t)MAXN * 32];
__device__ uint2 g_h0h[(size_t)MAXN * 32];
__device__ uint2 g_h1h[(size_t)MAXN * 32];
__device__ float g_m[(size_t)MAXN * D];      // fp32 m (fp16 overflows: |m|~1e5)
__device__ float g_hgA[MAXG * D];
__device__ float g_hgB[MAXG * D];
__device__ float g_ctx[MAXG * D];
__device__ float g_pg[MAXG * D];
__device__ float g_t[MAXG * D];
__device__ float g_lead[D];
__device__ int   g_rowptr[MAXN + 1];
__device__ int   g_cursor[MAXN];
__device__ int   g_csr[MAXE];
__device__ int   g_bsum[256];

__device__ __forceinline__ void red4(float* p, float4 v) {
    asm volatile("red.global.add.v4.f32 [%0], {%1,%2,%3,%4};"
                 :: "l"(p), "f"(v.x), "f"(v.y), "f"(v.z), "f"(v.w) : "memory");
}
__device__ __forceinline__ void red2(float* p, float x, float y) {
    asm volatile("red.global.add.v2.f32 [%0], {%1,%2};"
                 :: "l"(p), "f"(x), "f"(y) : "memory");
}
__device__ __forceinline__ float tf32r(float x) {
    float r;
    asm("cvt.rna.tf32.f32 %0, %1;" : "=f"(r) : "f"(x));
    return r;
}
__device__ __forceinline__ uint2 f42h(float4 v) {
    __half2 a = __floats2half2_rn(v.x, v.y);
    __half2 b = __floats2half2_rn(v.z, v.w);
    uint2 u;
    u.x = *(uint32_t*)&a;
    u.y = *(uint32_t*)&b;
    return u;
}
// accumulate 8 halves (uint4) into 8 fp32 accumulators
__device__ __forceinline__ void acc8(float* acc, uint4 u) {
    float2 f0 = __half22float2(*(__half2*)&u.x);
    float2 f1 = __half22float2(*(__half2*)&u.y);
    float2 f2 = __half22float2(*(__half2*)&u.z);
    float2 f3 = __half22float2(*(__half2*)&u.w);
    acc[0] += f0.x; acc[1] += f0.y; acc[2] += f1.x; acc[3] += f1.y;
    acc[4] += f2.x; acc[5] += f2.y; acc[6] += f3.x; acc[7] += f3.y;
}
__device__ __forceinline__ void mma_tf32(float* c, const uint32_t* a, uint32_t b0, uint32_t b1) {
    asm volatile(
        "mma.sync.aligned.m16n8k8.row.col.f32.tf32.tf32.f32 "
        "{%0,%1,%2,%3}, {%4,%5,%6,%7}, {%8,%9}, {%0,%1,%2,%3};"
        : "+f"(c[0]), "+f"(c[1]), "+f"(c[2]), "+f"(c[3])
        : "r"(a[0]), "r"(a[1]), "r"(a[2]), "r"(a[3]), "r"(b0), "r"(b1));
}

__global__ void k_zeroi(int* __restrict__ p, int n) {
    int i = blockIdx.x * blockDim.x + threadIdx.x;
    if (i < n) p[i] = 0;
}

// ================= CSR build =================
__global__ void k_hist(const int* __restrict__ dst, int* __restrict__ deg, int nE) {
    int e = blockIdx.x * blockDim.x + threadIdx.x;
    if (e < nE) atomicAdd(deg + __ldg(dst + e), 1);
}
__global__ void k_bsum(const int* __restrict__ deg, int* __restrict__ bsum, int n) {
    __shared__ int sh[8];
    int base = blockIdx.x * 1024 + threadIdx.x * 4;
    int s = 0;
    #pragma unroll
    for (int j = 0; j < 4; j++) { int i = base + j; if (i < n) s += deg[i]; }
    #pragma unroll
    for (int o = 16; o > 0; o >>= 1) s += __shfl_down_sync(0xffffffffu, s, o);
    if ((threadIdx.x & 31) == 0) sh[threadIdx.x >> 5] = s;
    __syncthreads();
    if (threadIdx.x == 0) {
        int t = 0;
        for (int w = 0; w < 8; w++) t += sh[w];
        bsum[blockIdx.x] = t;
    }
}
__global__ void k_scanblk(int* __restrict__ bsum, int nb, int* __restrict__ rowptr, int n, int nE) {
    __shared__ int ws[8];
    __shared__ int wexc[8];
    int tid = threadIdx.x;
    int lane = tid & 31, warp = tid >> 5;
    int v = (tid < nb) ? bsum[tid] : 0;
    int p = v;
    #pragma unroll
    for (int o = 1; o < 32; o <<= 1) {
        int t = __shfl_up_sync(0xffffffffu, p, o);
        if (lane >= o) p += t;
    }
    if (lane == 31) ws[warp] = p;
    __syncthreads();
    if (tid == 0) {
        int acc = 0;
        #pragma unroll
        for (int w = 0; w < 8; w++) { wexc[w] = acc; acc += ws[w]; }
        rowptr[n] = nE;
    }
    __syncthreads();
    if (tid < nb) bsum[tid] = p - v + wexc[warp];
}
__global__ void k_scanfin(int* __restrict__ deg, const int* __restrict__ bsum,
                          int* __restrict__ rowptr, int* __restrict__ cursor, int n) {
    __shared__ int wsum[8];
    __shared__ int wexc[8];
    int lane = threadIdx.x & 31, warp = threadIdx.x >> 5;
    int base = blockIdx.x * 1024 + threadIdx.x * 4;
    int v[4]; int s = 0;
    #pragma unroll
    for (int j = 0; j < 4; j++) { int i = base + j; v[j] = (i < n) ? deg[i] : 0; s += v[j]; }
    int pre = s;
    #pragma unroll
    for (int o = 1; o < 32; o <<= 1) {
        int t = __shfl_up_sync(0xffffffffu, pre, o);
        if (lane >= o) pre += t;
    }
    int excl = pre - s;
    if (lane == 31) wsum[warp] = pre;
    __syncthreads();
    if (threadIdx.x == 0) {
        int acc = 0;
        #pragma unroll
        for (int w = 0; w < 8; w++) { wexc[w] = acc; acc += wsum[w]; }
    }
    __syncthreads();
    int off = bsum[blockIdx.x] + wexc[warp] + excl;
    #pragma unroll
    for (int j = 0; j < 4; j++) {
        int i = base + j;
        if (i < n) { rowptr[i] = off; cursor[i] = off; off += v[j]; }
    }
}
__global__ void k_fill(const int* __restrict__ src, const int* __restrict__ dst,
                       int* __restrict__ cursor, int* __restrict__ csr, int nE) {
    int e = blockIdx.x * blockDim.x + threadIdx.x;
    if (e < nE) {
        int pos = atomicAdd(cursor + __ldg(dst + e), 1);
        csr[pos] = __ldg(src + e);
    }
}

// ================= context =================
__global__ void k_lead(const float* __restrict__ lf, float* __restrict__ lead, int nl) {
    int d = threadIdx.x;
    float a0 = 0.f, a1 = 0.f, a2 = 0.f, a3 = 0.f;
    int r = 0;
    for (; r + 3 < nl; r += 4) {
        a0 += lf[(r + 0) * D + d];
        a1 += lf[(r + 1) * D + d];
        a2 += lf[(r + 2) * D + d];
        a3 += lf[(r + 3) * D + d];
    }
    for (; r < nl; r++) a0 += lf[r * D + d];
    lead[d] = (a0 + a1) + (a2 + a3);
}
__global__ void k_initctx(float* __restrict__ ctx, float* __restrict__ hg,
                          const float* __restrict__ lead, int n) {
    int i = blockIdx.x * blockDim.x + threadIdx.x;
    if (i < n) { ctx[i] = lead[i & (D - 1)]; hg[i] = 0.f; }
}
// x scatter + fused fp16 conversion
__global__ void k_scatter_x(const float4* __restrict__ rows, const int* __restrict__ ids,
                            float* __restrict__ out, uint2* __restrict__ xh, int n) {
    int t = blockIdx.x * blockDim.x + threadIdx.x;
    int r = t >> 5, lane = t & 31;
    if (r >= n) return;
    int g = __ldg(ids + r);
    float4 v = __ldg(rows + (size_t)r * 32 + lane);
    xh[(size_t)r * 32 + lane] = f42h(v);
    red4(out + (size_t)g * D + lane * 4, v);
}
__global__ void k_scatter_rows(const float4* __restrict__ rows, const int* __restrict__ ids,
                               float* __restrict__ out, int n) {
    int t = blockIdx.x * blockDim.x + threadIdx.x;
    int r = t >> 5, lane = t & 31;
    if (r >= n) return;
    int g = __ldg(ids + r);
    float4 v = __ldg(rows + (size_t)r * 32 + lane);
    red4(out + (size_t)g * D + lane * 4, v);
}
__global__ void k_pg(const float* __restrict__ hg, const float* __restrict__ ctx,
                     const float* __restrict__ W, const float* __restrict__ Wc,
                     const float* __restrict__ b, float* __restrict__ pg,
                     float* __restrict__ hgNext) {
    int g = blockIdx.x, d = threadIdx.x;
    __shared__ float sh[D], sc[D];
    sh[d] = hg[g * D + d];
    sc[d] = ctx[g * D + d];
    __syncthreads();
    float acc = __ldg(b + d);
    #pragma unroll 8
    for (int k = 0; k < D; k++) {
        acc += sh[k] * __ldg(W + k * D + d);
        acc += sc[k] * __ldg(Wc + k * D + d);
    }
    pg[g * D + d] = acc;
    hgNext[g * D + d] = 0.f;
}
__global__ void k_fc(const float* __restrict__ in, const float* __restrict__ Wm,
                     const float* __restrict__ bias, float* __restrict__ out, int do_relu) {
    int g = blockIdx.x, d = threadIdx.x;
    __shared__ float s[D];
    s[d] = in[g * D + d];
    __syncthreads();
    float acc = __ldg(bias + d);
    #pragma unroll 8
    for (int k = 0; k < D; k++) acc += s[k] * __ldg(Wm + k * D + d);
    if (do_relu) acc = fmaxf(acc, 0.f);
    out[g * D + d] = acc;
}

// ====== gather v2: 2 nodes per warp, 16 lanes x uint4 (16B) per row ======
// m[v] = (1+eps)h[v] + sum_{u in N(v)} h[u]; fp16 in, fp32 accum + out.
__global__ void k_gather_h2(const uint4* __restrict__ h4, const int* __restrict__ rowptr,
                            const int* __restrict__ csr, float4* __restrict__ m4,
                            const float* __restrict__ epsArr, int l, int n) {
    int t = blockIdx.x * blockDim.x + threadIdx.x;
    int v = t >> 4;             // half-warp per node
    int sl = t & 15;            // sublane: 16B chunk of the 256B row
    if (v >= n) return;
    const float sc = 1.0f + __ldg(epsArr + l);
    int beg = __ldg(rowptr + v), end = __ldg(rowptr + v + 1);

    float acc[8];
    {
        uint4 hv = __ldg(h4 + (size_t)v * 16 + sl);
        float2 f0 = __half22float2(*(__half2*)&hv.x);
        float2 f1 = __half22float2(*(__half2*)&hv.y);
        float2 f2 = __half22float2(*(__half2*)&hv.z);
        float2 f3 = __half22float2(*(__half2*)&hv.w);
        acc[0] = sc * f0.x; acc[1] = sc * f0.y; acc[2] = sc * f1.x; acc[3] = sc * f1.y;
        acc[4] = sc * f2.x; acc[5] = sc * f2.y; acc[6] = sc * f3.x; acc[7] = sc * f3.y;
    }
    int i = beg;
    for (; i + 1 < end; i += 2) {
        int u0 = __ldg(csr + i), u1 = __ldg(csr + i + 1);
        uint4 a = __ldg(h4 + (size_t)u0 * 16 + sl);
        uint4 b = __ldg(h4 + (size_t)u1 * 16 + sl);
        acc8(acc, a);
        acc8(acc, b);
    }
    if (i < end) {
        int u0 = __ldg(csr + i);
        uint4 a = __ldg(h4 + (size_t)u0 * 16 + sl);
        acc8(acc, a);
    }
    // row elements sl*8 .. sl*8+7 -> float4 indices sl*2, sl*2+1
    m4[(size_t)v * 32 + sl * 2]     = make_float4(acc[0], acc[1], acc[2], acc[3]);
    m4[(size_t)v * 32 + sl * 2 + 1] = make_float4(acc[4], acc[5], acc[6], acc[7]);
}

// ================= node GEMM: mma.sync tf32 (proven R11) =================
#define ASTRIDE 132
#define BSTRIDE 136
#define SMEM_GEMM ((128 * ASTRIDE + 128 * BSTRIDE) * 4)
__global__ void __launch_bounds__(256, 1)
k_gemm(const float4* __restrict__ M4, const float4* __restrict__ Wl4,
       const float* __restrict__ pgv, const int* __restrict__ gid,
       uint32_t* __restrict__ HoutH, float* __restrict__ hgOut, int nRows, int storeH) {
    extern __shared__ float smem[];
    float* As = smem;                       // [128][132]  m x k
    float* Bs = smem + 128 * ASTRIDE;       // [128][136]  k x n
    const int tid = threadIdx.x;
    const int wid = tid >> 5, lane = tid & 31;
    const int m0 = blockIdx.x * 128;
    const int warpM = (wid & 3) * 32;
    const int warpN = (wid >> 2) * 64;
    const int lr = lane >> 2, lc = lane & 3;

    #pragma unroll
    for (int i = 0; i < 16; i++) {
        int li = tid + i * 256;
        int row = li >> 5, k4 = li & 31;
        int mg = m0 + row;
        float4 v = (mg < nRows) ? __ldg(M4 + (size_t)mg * 32 + k4)
                                : make_float4(0.f, 0.f, 0.f, 0.f);
        v.x = tf32r(v.x); v.y = tf32r(v.y); v.z = tf32r(v.z); v.w = tf32r(v.w);
        *(float4*)(As + row * ASTRIDE + k4 * 4) = v;
    }
    #pragma unroll
    for (int i = 0; i < 16; i++) {
        int li = tid + i * 256;
        int k = li >> 5, n4 = li & 31;
        float4 v = __ldg(Wl4 + k * 32 + n4);
        v.x = tf32r(v.x); v.y = tf32r(v.y); v.z = tf32r(v.z); v.w = tf32r(v.w);
        *(float4*)(Bs + k * BSTRIDE + n4 * 4) = v;
    }
    __syncthreads();

    float acc[2][8][4];
    #pragma unroll
    for (int mt = 0; mt < 2; mt++)
        #pragma unroll
        for (int j = 0; j < 8; j++)
            #pragma unroll
            for (int q = 0; q < 4; q++) acc[mt][j][q] = 0.f;

    const uint32_t* Au = (const uint32_t*)As;
    const uint32_t* Bu = (const uint32_t*)Bs;

    #pragma unroll
    for (int ks = 0; ks < 16; ks++) {
        const int kb = ks * 8;
        uint32_t a[2][4];
        #pragma unroll
        for (int mt = 0; mt < 2; mt++) {
            int r0 = warpM + mt * 16 + lr;
            a[mt][0] = Au[r0 * ASTRIDE + kb + lc];
            a[mt][1] = Au[(r0 + 8) * ASTRIDE + kb + lc];
            a[mt][2] = Au[r0 * ASTRIDE + kb + lc + 4];
            a[mt][3] = Au[(r0 + 8) * ASTRIDE + kb + lc + 4];
        }
        #pragma unroll
        for (int j = 0; j < 8; j++) {
            int nc = warpN + j * 8 + lr;
            uint32_t b0 = Bu[(kb + lc) * BSTRIDE + nc];
            uint32_t b1 = Bu[(kb + lc + 4) * BSTRIDE + nc];
            mma_tf32(acc[0][j], a[0], b0, b1);
            mma_tf32(acc[1][j], a[1], b0, b1);
        }
    }

    #pragma unroll
    for (int mt = 0; mt < 2; mt++) {
        #pragma unroll
        for (int half = 0; half < 2; half++) {
            int mg = m0 + warpM + mt * 16 + half * 8 + lr;
            if (mg >= nRows) continue;
            int g = __ldg(gid + mg);
            const float* pgr = pgv + (size_t)g * D;
            #pragma unroll
            for (int j = 0; j < 8; j++) {
                int nc = warpN + j * 8 + lc * 2;
                float c0 = acc[mt][j][half * 2 + 0];
                float c1 = acc[mt][j][half * 2 + 1];
                float2 p = __ldg((const float2*)(pgr + nc));
                float o0 = fmaxf(c0 + p.x, 0.f);
                float o1 = fmaxf(c1 + p.y, 0.f);
                if (storeH) {
                    __half2 hv = __floats2half2_rn(o0, o1);
                    HoutH[((size_t)mg * D + nc) >> 1] = *(uint32_t*)&hv;
                }
                red2(hgOut + (size_t)g * D + nc, o0, o1);
            }
        }
    }
}

extern "C" void kernel_launch(void* const* d_in, const int* in_sizes, int n_in,
                              void* d_out, int out_size) {
    const float* x        = (const float*)d_in[0];
    const int*   src      = (const int*)d_in[1];
    const int*   dst      = (const int*)d_in[2];
    const int*   gids     = (const int*)d_in[3];
    const float* initf    = (const float*)d_in[4];
    const int*   init_ids = (const int*)d_in[5];
    const float* leadf    = (const float*)d_in[6];
    const float* W        = (const float*)d_in[7];
    const float* Wc       = (const float*)d_in[8];
    const float* b        = (const float*)d_in[9];
    const float* eps      = (const float*)d_in[10];
    const float* fc1_w    = (const float*)d_in[11];
    const float* fc1_b    = (const float*)d_in[12];
    const float* fc2_w    = (const float*)d_in[13];
    const float* fc2_b    = (const float*)d_in[14];

    const int N  = in_sizes[0] / D;
    const int E  = in_sizes[1];
    const int NI = in_sizes[4] / D;
    const int NL = in_sizes[6] / D;
    const int L  = in_sizes[10];
    const int G  = out_size / D;

    uint2 *xh, *h0h, *h1h;
    float *mbuf, *hgA, *hgB, *ctx, *pg, *tbuf, *lead;
    int *rowptr, *cursor, *csr, *bsum;
    cudaGetSymbolAddress((void**)&xh, g_xh);
    cudaGetSymbolAddress((void**)&h0h, g_h0h);
    cudaGetSymbolAddress((void**)&h1h, g_h1h);
    cudaGetSymbolAddress((void**)&mbuf, g_m);
    cudaGetSymbolAddress((void**)&hgA, g_hgA);
    cudaGetSymbolAddress((void**)&hgB, g_hgB);
    cudaGetSymbolAddress((void**)&ctx, g_ctx);
    cudaGetSymbolAddress((void**)&pg, g_pg);
    cudaGetSymbolAddress((void**)&tbuf, g_t);
    cudaGetSymbolAddress((void**)&lead, g_lead);
    cudaGetSymbolAddress((void**)&rowptr, g_rowptr);
    cudaGetSymbolAddress((void**)&cursor, g_cursor);
    cudaGetSymbolAddress((void**)&csr, g_csr);
    cudaGetSymbolAddress((void**)&bsum, g_bsum);

    cudaFuncSetAttribute(k_gemm, cudaFuncAttributeMaxDynamicSharedMemorySize, SMEM_GEMM);

    const int NB = (N + 1023) / 1024;

    // CSR build
    k_zeroi<<<(N + 255) / 256, 256>>>(cursor, N);
    k_hist<<<(E + 255) / 256, 256>>>(dst, cursor, E);
    k_bsum<<<NB, 256>>>(cursor, bsum, N);
    k_scanblk<<<1, 256>>>(bsum, NB, rowptr, N, E);
    k_scanfin<<<NB, 256>>>(cursor, bsum, rowptr, cursor, N);
    k_fill<<<(E + 255) / 256, 256>>>(src, dst, cursor, csr, E);

    // context (+ fused x->fp16)
    k_lead<<<1, D>>>(leadf, lead, NL);
    k_initctx<<<(G * D + 255) / 256, 256>>>(ctx, hgA, lead, G * D);
    k_scatter_x<<<(N * 32 + 255) / 256, 256>>>((const float4*)x, gids, hgA, xh, N);
    k_scatter_rows<<<(NI * 32 + 255) / 256, 256>>>((const float4*)initf, init_ids, ctx, NI);

    const uint2* hin = xh;
    uint2* hbuf[2] = {h0h, h1h};
    float* hg_in = hgA;
    float* hg_out = hgB;

    for (int l = 0; l < L; l++) {
        uint2* hout = hbuf[l & 1];
        int storeH = (l + 1 < L) ? 1 : 0;
        k_gather_h2<<<(N * 16 + 255) / 256, 256>>>((const uint4*)hin, rowptr, csr,
                                                   (float4*)mbuf, eps, l, N);
        k_pg<<<G, D>>>(hg_in, ctx, W + (size_t)l * D * D, Wc + (size_t)l * D * D,
                       b + l * D, pg, hg_out);
        k_gemm<<<(N + 127) / 128, 256, SMEM_GEMM>>>(
            (const float4*)mbuf, (const float4*)(W + (size_t)l * D * D),
            pg, gids, (uint32_t*)hout, hg_out, N, storeH);
        hin = hout;
        float* tmp = hg_in; hg_in = hg_out; hg_out = tmp;
    }

    k_fc<<<G, D>>>(hg_in, fc1_w, fc1_b, tbuf, 1);
    k_fc<<<G, D>>>(tbuf, fc2_w, fc2_b, (float*)d_out, 0);
}

// round 14
// speedup vs baseline: 3.4705x; 1.0501x over previous
#include <cuda_runtime.h>
#include <cuda_fp16.h>
#include <cstdint>

// GGIN: 3-layer GIN + graph readout. N=100000, E=1600000, D=128, G=1024, L=3, C=128.
// R13: per-graph GEMMs (pg, fc1, fc2) moved to mma.sync tf32 tile kernels
//      (kills the 134MB/layer W re-read of the old per-graph-block kernels).
//      Gather = R12 half-warp fp16, neighbor loop unrolled x4.

#define D 128
#define MAXN 100000
#define MAXG 1024
#define MAXE 1600000

__device__ uint2 g_xh[(size_t)MAXN * 32];
__device__ uint2 g_h0h[(size_t)MAXN * 32];
__device__ uint2 g_h1h[(size_t)MAXN * 32];
__device__ float g_m[(size_t)MAXN * D];      // fp32 m (fp16 overflows: |m|~1e5)
__device__ float g_hgA[MAXG * D];
__device__ float g_hgB[MAXG * D];
__device__ float g_ctx[MAXG * D];
__device__ float g_pg[MAXG * D];
__device__ float g_t[MAXG * D];
__device__ float g_lead[D];
__device__ int   g_rowptr[MAXN + 1];
__device__ int   g_cursor[MAXN];
__device__ int   g_csr[MAXE];
__device__ int   g_bsum[256];

__device__ __forceinline__ void red4(float* p, float4 v) {
    asm volatile("red.global.add.v4.f32 [%0], {%1,%2,%3,%4};"
                 :: "l"(p), "f"(v.x), "f"(v.y), "f"(v.z), "f"(v.w) : "memory");
}
__device__ __forceinline__ void red2(float* p, float x, float y) {
    asm volatile("red.global.add.v2.f32 [%0], {%1,%2};"
                 :: "l"(p), "f"(x), "f"(y) : "memory");
}
__device__ __forceinline__ float tf32r(float x) {
    float r;
    asm("cvt.rna.tf32.f32 %0, %1;" : "=f"(r) : "f"(x));
    return r;
}
__device__ __forceinline__ uint2 f42h(float4 v) {
    __half2 a = __floats2half2_rn(v.x, v.y);
    __half2 b = __floats2half2_rn(v.z, v.w);
    uint2 u;
    u.x = *(uint32_t*)&a;
    u.y = *(uint32_t*)&b;
    return u;
}
__device__ __forceinline__ void acc8(float* acc, uint4 u) {
    float2 f0 = __half22float2(*(__half2*)&u.x);
    float2 f1 = __half22float2(*(__half2*)&u.y);
    float2 f2 = __half22float2(*(__half2*)&u.z);
    float2 f3 = __half22float2(*(__half2*)&u.w);
    acc[0] += f0.x; acc[1] += f0.y; acc[2] += f1.x; acc[3] += f1.y;
    acc[4] += f2.x; acc[5] += f2.y; acc[6] += f3.x; acc[7] += f3.y;
}
__device__ __forceinline__ void mma_tf32(float* c, const uint32_t* a, uint32_t b0, uint32_t b1) {
    asm volatile(
        "mma.sync.aligned.m16n8k8.row.col.f32.tf32.tf32.f32 "
        "{%0,%1,%2,%3}, {%4,%5,%6,%7}, {%8,%9}, {%0,%1,%2,%3};"
        : "+f"(c[0]), "+f"(c[1]), "+f"(c[2]), "+f"(c[3])
        : "r"(a[0]), "r"(a[1]), "r"(a[2]), "r"(a[3]), "r"(b0), "r"(b1));
}

#define ASTRIDE 132
#define BSTRIDE 136
#define SMEM_GEMM ((128 * ASTRIDE + 128 * BSTRIDE) * 4)

// load a 128x128 fp32 tile (row-major, 32 float4/row) into smem with tf32 rounding
__device__ __forceinline__ void load_tile_tf32(const float4* __restrict__ src,
                                               float* __restrict__ dst, int stride, int tid) {
    #pragma unroll
    for (int i = 0; i < 16; i++) {
        int li = tid + i * 256;
        int r = li >> 5, c4 = li & 31;
        float4 v = __ldg(src + r * 32 + c4);
        v.x = tf32r(v.x); v.y = tf32r(v.y); v.z = tf32r(v.z); v.w = tf32r(v.w);
        *(float4*)(dst + r * stride + c4 * 4) = v;
    }
}
// shared mma mainloop: 128x128x128, warp tile 32x64
__device__ __forceinline__ void mma_mainloop(const uint32_t* __restrict__ Au,
                                             const uint32_t* __restrict__ Bu,
                                             float acc[2][8][4], int warpM, int warpN,
                                             int lr, int lc) {
    #pragma unroll
    for (int ks = 0; ks < 16; ks++) {
        const int kb = ks * 8;
        uint32_t a[2][4];
        #pragma unroll
        for (int mt = 0; mt < 2; mt++) {
            int r0 = warpM + mt * 16 + lr;
            a[mt][0] = Au[r0 * ASTRIDE + kb + lc];
            a[mt][1] = Au[(r0 + 8) * ASTRIDE + kb + lc];
            a[mt][2] = Au[r0 * ASTRIDE + kb + lc + 4];
            a[mt][3] = Au[(r0 + 8) * ASTRIDE + kb + lc + 4];
        }
        #pragma unroll
        for (int j = 0; j < 8; j++) {
            int nc = warpN + j * 8 + lr;
            uint32_t b0 = Bu[(kb + lc) * BSTRIDE + nc];
            uint32_t b1 = Bu[(kb + lc + 4) * BSTRIDE + nc];
            mma_tf32(acc[0][j], a[0], b0, b1);
            mma_tf32(acc[1][j], a[1], b0, b1);
        }
    }
}

__global__ void k_zeroi(int* __restrict__ p, int n) {
    int i = blockIdx.x * blockDim.x + threadIdx.x;
    if (i < n) p[i] = 0;
}

// ================= CSR build =================
__global__ void k_hist(const int* __restrict__ dst, int* __restrict__ deg, int nE) {
    int e = blockIdx.x * blockDim.x + threadIdx.x;
    if (e < nE) atomicAdd(deg + __ldg(dst + e), 1);
}
__global__ void k_bsum(const int* __restrict__ deg, int* __restrict__ bsum, int n) {
    __shared__ int sh[8];
    int base = blockIdx.x * 1024 + threadIdx.x * 4;
    int s = 0;
    #pragma unroll
    for (int j = 0; j < 4; j++) { int i = base + j; if (i < n) s += deg[i]; }
    #pragma unroll
    for (int o = 16; o > 0; o >>= 1) s += __shfl_down_sync(0xffffffffu, s, o);
    if ((threadIdx.x & 31) == 0) sh[threadIdx.x >> 5] = s;
    __syncthreads();
    if (threadIdx.x == 0) {
        int t = 0;
        for (int w = 0; w < 8; w++) t += sh[w];
        bsum[blockIdx.x] = t;
    }
}
__global__ void k_scanblk(int* __restrict__ bsum, int nb, int* __restrict__ rowptr, int n, int nE) {
    __shared__ int ws[8];
    __shared__ int wexc[8];
    int tid = threadIdx.x;
    int lane = tid & 31, warp = tid >> 5;
    int v = (tid < nb) ? bsum[tid] : 0;
    int p = v;
    #pragma unroll
    for (int o = 1; o < 32; o <<= 1) {
        int t = __shfl_up_sync(0xffffffffu, p, o);
        if (lane >= o) p += t;
    }
    if (lane == 31) ws[warp] = p;
    __syncthreads();
    if (tid == 0) {
        int acc = 0;
        #pragma unroll
        for (int w = 0; w < 8; w++) { wexc[w] = acc; acc += ws[w]; }
        rowptr[n] = nE;
    }
    __syncthreads();
    if (tid < nb) bsum[tid] = p - v + wexc[warp];
}
__global__ void k_scanfin(int* __restrict__ deg, const int* __restrict__ bsum,
                          int* __restrict__ rowptr, int* __restrict__ cursor, int n) {
    __shared__ int wsum[8];
    __shared__ int wexc[8];
    int lane = threadIdx.x & 31, warp = threadIdx.x >> 5;
    int base = blockIdx.x * 1024 + threadIdx.x * 4;
    int v[4]; int s = 0;
    #pragma unroll
    for (int j = 0; j < 4; j++) { int i = base + j; v[j] = (i < n) ? deg[i] : 0; s += v[j]; }
    int pre = s;
    #pragma unroll
    for (int o = 1; o < 32; o <<= 1) {
        int t = __shfl_up_sync(0xffffffffu, pre, o);
        if (lane >= o) pre += t;
    }
    int excl = pre - s;
    if (lane == 31) wsum[warp] = pre;
    __syncthreads();
    if (threadIdx.x == 0) {
        int acc = 0;
        #pragma unroll
        for (int w = 0; w < 8; w++) { wexc[w] = acc; acc += wsum[w]; }
    }
    __syncthreads();
    int off = bsum[blockIdx.x] + wexc[warp] + excl;
    #pragma unroll
    for (int j = 0; j < 4; j++) {
        int i = base + j;
        if (i < n) { rowptr[i] = off; cursor[i] = off; off += v[j]; }
    }
}
__global__ void k_fill(const int* __restrict__ src, const int* __restrict__ dst,
                       int* __restrict__ cursor, int* __restrict__ csr, int nE) {
    int e = blockIdx.x * blockDim.x + threadIdx.x;
    if (e < nE) {
        int pos = atomicAdd(cursor + __ldg(dst + e), 1);
        csr[pos] = __ldg(src + e);
    }
}

// ================= context =================
__global__ void k_lead(const float* __restrict__ lf, float* __restrict__ lead, int nl) {
    int d = threadIdx.x;
    float a0 = 0.f, a1 = 0.f, a2 = 0.f, a3 = 0.f;
    int r = 0;
    for (; r + 3 < nl; r += 4) {
        a0 += lf[(r + 0) * D + d];
        a1 += lf[(r + 1) * D + d];
        a2 += lf[(r + 2) * D + d];
        a3 += lf[(r + 3) * D + d];
    }
    for (; r < nl; r++) a0 += lf[r * D + d];
    lead[d] = (a0 + a1) + (a2 + a3);
}
__global__ void k_initctx(float* __restrict__ ctx, float* __restrict__ hg,
                          const float* __restrict__ lead, int n) {
    int i = blockIdx.x * blockDim.x + threadIdx.x;
    if (i < n) { ctx[i] = lead[i & (D - 1)]; hg[i] = 0.f; }
}
__global__ void k_scatter_x(const float4* __restrict__ rows, const int* __restrict__ ids,
                            float* __restrict__ out, uint2* __restrict__ xh, int n) {
    int t = blockIdx.x * blockDim.x + threadIdx.x;
    int r = t >> 5, lane = t & 31;
    if (r >= n) return;
    int g = __ldg(ids + r);
    float4 v = __ldg(rows + (size_t)r * 32 + lane);
    xh[(size_t)r * 32 + lane] = f42h(v);
    red4(out + (size_t)g * D + lane * 4, v);
}
__global__ void k_scatter_rows(const float4* __restrict__ rows, const int* __restrict__ ids,
                               float* __restrict__ out, int n) {
    int t = blockIdx.x * blockDim.x + threadIdx.x;
    int r = t >> 5, lane = t & 31;
    if (r >= n) return;
    int g = __ldg(ids + r);
    float4 v = __ldg(rows + (size_t)r * 32 + lane);
    red4(out + (size_t)g * D + lane * 4, v);
}

// ====== pg via mma: pg = hg@W + ctx@Wc + b; also zero hgNext. grid = G/128 ======
__global__ void __launch_bounds__(256, 1)
k_pgmma(const float4* __restrict__ hg4, const float4* __restrict__ ctx4,
        const float4* __restrict__ W4, const float4* __restrict__ Wc4,
        const float* __restrict__ bias, float* __restrict__ pg,
        float* __restrict__ hgNext) {
    extern __shared__ float smem[];
    float* As = smem;
    float* Bs = smem + 128 * ASTRIDE;
    const int tid = threadIdx.x;
    const int wid = tid >> 5, lane = tid & 31;
    const int g0 = blockIdx.x * 128;
    const int warpM = (wid & 3) * 32;
    const int warpN = (wid >> 2) * 64;
    const int lr = lane >> 2, lc = lane & 3;

    float acc[2][8][4];
    #pragma unroll
    for (int mt = 0; mt < 2; mt++)
        #pragma unroll
        for (int j = 0; j < 8; j++)
            #pragma unroll
            for (int q = 0; q < 4; q++) acc[mt][j][q] = 0.f;

    // pass 1: hg @ W
    load_tile_tf32(hg4 + (size_t)g0 * 32, As, ASTRIDE, tid);
    load_tile_tf32(W4, Bs, BSTRIDE, tid);
    __syncthreads();
    mma_mainloop((const uint32_t*)As, (const uint32_t*)Bs, acc, warpM, warpN, lr, lc);
    __syncthreads();
    // pass 2: ctx @ Wc (accumulate)
    load_tile_tf32(ctx4 + (size_t)g0 * 32, As, ASTRIDE, tid);
    load_tile_tf32(Wc4, Bs, BSTRIDE, tid);
    __syncthreads();
    mma_mainloop((const uint32_t*)As, (const uint32_t*)Bs, acc, warpM, warpN, lr, lc);

    #pragma unroll
    for (int mt = 0; mt < 2; mt++) {
        #pragma unroll
        for (int half = 0; half < 2; half++) {
            int mg = g0 + warpM + mt * 16 + half * 8 + lr;
            #pragma unroll
            for (int j = 0; j < 8; j++) {
                int nc = warpN + j * 8 + lc * 2;
                float2 bv = __ldg((const float2*)(bias + nc));
                float2 o;
                o.x = acc[mt][j][half * 2 + 0] + bv.x;
                o.y = acc[mt][j][half * 2 + 1] + bv.y;
                *(float2*)(pg + (size_t)mg * D + nc) = o;
                *(float2*)(hgNext + (size_t)mg * D + nc) = make_float2(0.f, 0.f);
            }
        }
    }
}

// ====== fc via mma: out = (relu?)(in@W + bias). grid = G/128 ======
__global__ void __launch_bounds__(256, 1)
k_fcmma(const float4* __restrict__ in4, const float4* __restrict__ W4,
        const float* __restrict__ bias, float* __restrict__ out, int do_relu) {
    extern __shared__ float smem[];
    float* As = smem;
    float* Bs = smem + 128 * ASTRIDE;
    const int tid = threadIdx.x;
    const int wid = tid >> 5, lane = tid & 31;
    const int g0 = blockIdx.x * 128;
    const int warpM = (wid & 3) * 32;
    const int warpN = (wid >> 2) * 64;
    const int lr = lane >> 2, lc = lane & 3;

    float acc[2][8][4];
    #pragma unroll
    for (int mt = 0; mt < 2; mt++)
        #pragma unroll
        for (int j = 0; j < 8; j++)
            #pragma unroll
            for (int q = 0; q < 4; q++) acc[mt][j][q] = 0.f;

    load_tile_tf32(in4 + (size_t)g0 * 32, As, ASTRIDE, tid);
    load_tile_tf32(W4, Bs, BSTRIDE, tid);
    __syncthreads();
    mma_mainloop((const uint32_t*)As, (const uint32_t*)Bs, acc, warpM, warpN, lr, lc);

    #pragma unroll
    for (int mt = 0; mt < 2; mt++) {
        #pragma unroll
        for (int half = 0; half < 2; half++) {
            int mg = g0 + warpM + mt * 16 + half * 8 + lr;
            #pragma unroll
            for (int j = 0; j < 8; j++) {
                int nc = warpN + j * 8 + lc * 2;
                float2 bv = __ldg((const float2*)(bias + nc));
                float o0 = acc[mt][j][half * 2 + 0] + bv.x;
                float o1 = acc[mt][j][half * 2 + 1] + bv.y;
                if (do_relu) { o0 = fmaxf(o0, 0.f); o1 = fmaxf(o1, 0.f); }
                *(float2*)(out + (size_t)mg * D + nc) = make_float2(o0, o1);
            }
        }
    }
}

// ====== gather: 2 nodes/warp, 16 lanes x uint4; neighbor loop unrolled x4 ======
__global__ void k_gather_h2(const uint4* __restrict__ h4, const int* __restrict__ rowptr,
                            const int* __restrict__ csr, float4* __restrict__ m4,
                            const float* __restrict__ epsArr, int l, int n) {
    int t = blockIdx.x * blockDim.x + threadIdx.x;
    int v = t >> 4;
    int sl = t & 15;
    if (v >= n) return;
    const float sc = 1.0f + __ldg(epsArr + l);
    int beg = __ldg(rowptr + v), end = __ldg(rowptr + v + 1);

    float acc[8];
    {
        uint4 hv = __ldg(h4 + (size_t)v * 16 + sl);
        float2 f0 = __half22float2(*(__half2*)&hv.x);
        float2 f1 = __half22float2(*(__half2*)&hv.y);
        float2 f2 = __half22float2(*(__half2*)&hv.z);
        float2 f3 = __half22float2(*(__half2*)&hv.w);
        acc[0] = sc * f0.x; acc[1] = sc * f0.y; acc[2] = sc * f1.x; acc[3] = sc * f1.y;
        acc[4] = sc * f2.x; acc[5] = sc * f2.y; acc[6] = sc * f3.x; acc[7] = sc * f3.y;
    }
    int i = beg;
    for (; i + 3 < end; i += 4) {
        int u0 = __ldg(csr + i), u1 = __ldg(csr + i + 1);
        int u2 = __ldg(csr + i + 2), u3 = __ldg(csr + i + 3);
        uint4 a = __ldg(h4 + (size_t)u0 * 16 + sl);
        uint4 b = __ldg(h4 + (size_t)u1 * 16 + sl);
        uint4 c = __ldg(h4 + (size_t)u2 * 16 + sl);
        uint4 d = __ldg(h4 + (size_t)u3 * 16 + sl);
        acc8(acc, a); acc8(acc, b); acc8(acc, c); acc8(acc, d);
    }
    for (; i < end; i++) {
        int u0 = __ldg(csr + i);
        uint4 a = __ldg(h4 + (size_t)u0 * 16 + sl);
        acc8(acc, a);
    }
    m4[(size_t)v * 32 + sl * 2]     = make_float4(acc[0], acc[1], acc[2], acc[3]);
    m4[(size_t)v * 32 + sl * 2 + 1] = make_float4(acc[4], acc[5], acc[6], acc[7]);
}

// ================= node GEMM: mma.sync tf32 (proven R11) =================
__global__ void __launch_bounds__(256, 1)
k_gemm(const float4* __restrict__ M4, const float4* __restrict__ Wl4,
       const float* __restrict__ pgv, const int* __restrict__ gid,
       uint32_t* __restrict__ HoutH, float* __restrict__ hgOut, int nRows, int storeH) {
    extern __shared__ float smem[];
    float* As = smem;
    float* Bs = smem + 128 * ASTRIDE;
    const int tid = threadIdx.x;
    const int wid = tid >> 5, lane = tid & 31;
    const int m0 = blockIdx.x * 128;
    const int warpM = (wid & 3) * 32;
    const int warpN = (wid >> 2) * 64;
    const int lr = lane >> 2, lc = lane & 3;

    #pragma unroll
    for (int i = 0; i < 16; i++) {
        int li = tid + i * 256;
        int row = li >> 5, k4 = li & 31;
        int mg = m0 + row;
        float4 v = (mg < nRows) ? __ldg(M4 + (size_t)mg * 32 + k4)
                                : make_float4(0.f, 0.f, 0.f, 0.f);
        v.x = tf32r(v.x); v.y = tf32r(v.y); v.z = tf32r(v.z); v.w = tf32r(v.w);
        *(float4*)(As + row * ASTRIDE + k4 * 4) = v;
    }
    load_tile_tf32(Wl4, Bs, BSTRIDE, tid);
    __syncthreads();

    float acc[2][8][4];
    #pragma unroll
    for (int mt = 0; mt < 2; mt++)
        #pragma unroll
        for (int j = 0; j < 8; j++)
            #pragma unroll
            for (int q = 0; q < 4; q++) acc[mt][j][q] = 0.f;

    mma_mainloop((const uint32_t*)As, (const uint32_t*)Bs, acc, warpM, warpN, lr, lc);

    #pragma unroll
    for (int mt = 0; mt < 2; mt++) {
        #pragma unroll
        for (int half = 0; half < 2; half++) {
            int mg = m0 + warpM + mt * 16 + half * 8 + lr;
            if (mg >= nRows) continue;
            int g = __ldg(gid + mg);
            const float* pgr = pgv + (size_t)g * D;
            #pragma unroll
            for (int j = 0; j < 8; j++) {
                int nc = warpN + j * 8 + lc * 2;
                float c0 = acc[mt][j][half * 2 + 0];
                float c1 = acc[mt][j][half * 2 + 1];
                float2 p = __ldg((const float2*)(pgr + nc));
                float o0 = fmaxf(c0 + p.x, 0.f);
                float o1 = fmaxf(c1 + p.y, 0.f);
                if (storeH) {
                    __half2 hv = __floats2half2_rn(o0, o1);
                    HoutH[((size_t)mg * D + nc) >> 1] = *(uint32_t*)&hv;
                }
                red2(hgOut + (size_t)g * D + nc, o0, o1);
            }
        }
    }
}

extern "C" void kernel_launch(void* const* d_in, const int* in_sizes, int n_in,
                              void* d_out, int out_size) {
    const float* x        = (const float*)d_in[0];
    const int*   src      = (const int*)d_in[1];
    const int*   dst      = (const int*)d_in[2];
    const int*   gids     = (const int*)d_in[3];
    const float* initf    = (const float*)d_in[4];
    const int*   init_ids = (const int*)d_in[5];
    const float* leadf    = (const float*)d_in[6];
    const float* W        = (const float*)d_in[7];
    const float* Wc       = (const float*)d_in[8];
    const float* b        = (const float*)d_in[9];
    const float* eps      = (const float*)d_in[10];
    const float* fc1_w    = (const float*)d_in[11];
    const float* fc1_b    = (const float*)d_in[12];
    const float* fc2_w    = (const float*)d_in[13];
    const float* fc2_b    = (const float*)d_in[14];

    const int N  = in_sizes[0] / D;
    const int E  = in_sizes[1];
    const int NI = in_sizes[4] / D;
    const int NL = in_sizes[6] / D;
    const int L  = in_sizes[10];
    const int G  = out_size / D;

    uint2 *xh, *h0h, *h1h;
    float *mbuf, *hgA, *hgB, *ctx, *pg, *tbuf, *lead;
    int *rowptr, *cursor, *csr, *bsum;
    cudaGetSymbolAddress((void**)&xh, g_xh);
    cudaGetSymbolAddress((void**)&h0h, g_h0h);
    cudaGetSymbolAddress((void**)&h1h, g_h1h);
    cudaGetSymbolAddress((void**)&mbuf, g_m);
    cudaGetSymbolAddress((void**)&hgA, g_hgA);
    cudaGetSymbolAddress((void**)&hgB, g_hgB);
    cudaGetSymbolAddress((void**)&ctx, g_ctx);
    cudaGetSymbolAddress((void**)&pg, g_pg);
    cudaGetSymbolAddress((void**)&tbuf, g_t);
    cudaGetSymbolAddress((void**)&lead, g_lead);
    cudaGetSymbolAddress((void**)&rowptr, g_rowptr);
    cudaGetSymbolAddress((void**)&cursor, g_cursor);
    cudaGetSymbolAddress((void**)&csr, g_csr);
    cudaGetSymbolAddress((void**)&bsum, g_bsum);

    cudaFuncSetAttribute(k_gemm, cudaFuncAttributeMaxDynamicSharedMemorySize, SMEM_GEMM);
    cudaFuncSetAttribute(k_pgmma, cudaFuncAttributeMaxDynamicSharedMemorySize, SMEM_GEMM);
    cudaFuncSetAttribute(k_fcmma, cudaFuncAttributeMaxDynamicSharedMemorySize, SMEM_GEMM);

    const int NB = (N + 1023) / 1024;
    const int GB = G / 128;   // G=1024 -> 8 blocks

    // CSR build
    k_zeroi<<<(N + 255) / 256, 256>>>(cursor, N);
    k_hist<<<(E + 255) / 256, 256>>>(dst, cursor, E);
    k_bsum<<<NB, 256>>>(cursor, bsum, N);
    k_scanblk<<<1, 256>>>(bsum, NB, rowptr, N, E);
    k_scanfin<<<NB, 256>>>(cursor, bsum, rowptr, cursor, N);
    k_fill<<<(E + 255) / 256, 256>>>(src, dst, cursor, csr, E);

    // context (+ fused x->fp16)
    k_lead<<<1, D>>>(leadf, lead, NL);
    k_initctx<<<(G * D + 255) / 256, 256>>>(ctx, hgA, lead, G * D);
    k_scatter_x<<<(N * 32 + 255) / 256, 256>>>((const float4*)x, gids, hgA, xh, N);
    k_scatter_rows<<<(NI * 32 + 255) / 256, 256>>>((const float4*)initf, init_ids, ctx, NI);

    const uint2* hin = xh;
    uint2* hbuf[2] = {h0h, h1h};
    float* hg_in = hgA;
    float* hg_out = hgB;

    for (int l = 0; l < L; l++) {
        uint2* hout = hbuf[l & 1];
        int storeH = (l + 1 < L) ? 1 : 0;
        k_gather_h2<<<(N * 16 + 255) / 256, 256>>>((const uint4*)hin, rowptr, csr,
                                                   (float4*)mbuf, eps, l, N);
        k_pgmma<<<GB, 256, SMEM_GEMM>>>(
            (const float4*)hg_in, (const float4*)ctx,
            (const float4*)(W + (size_t)l * D * D), (const float4*)(Wc + (size_t)l * D * D),
            b + l * D, pg, hg_out);
        k_gemm<<<(N + 127) / 128, 256, SMEM_GEMM>>>(
            (const float4*)mbuf, (const float4*)(W + (size_t)l * D * D),
            pg, gids, (uint32_t*)hout, hg_out, N, storeH);
        hin = hout;
        float* tmp = hg_in; hg_in = hg_out; hg_out = tmp;
    }

    k_fcmma<<<GB, 256, SMEM_GEMM>>>((const float4*)hg_in, (const float4*)fc1_w,
                                    fc1_b, tbuf, 1);
    k_fcmma<<<GB, 256, SMEM_GEMM>>>((const float4*)tbuf, (const float4*)fc2_w,
                                    fc2_b, (float*)d_out, 0);
}